// round 1
// baseline (speedup 1.0000x reference)
#include <cuda_runtime.h>
#include <math.h>

// Problem constants (fixed by the reference)
#define BATCH   4
#define S_LEN   2048
#define NHEAD   16
#define DH      64
#define DM      1024      // NHEAD*DH
#define BHTOT   (BATCH*NHEAD)   // 64
#define MROWS   (BATCH*S_LEN)   // 8192

// Scratch (device globals: allocation-free, graph-capturable)
__device__ float g_q[(size_t)BHTOT * S_LEN * DH];   // [b*16+h][s][d]
__device__ float g_k[(size_t)BHTOT * S_LEN * DH];
__device__ float g_v[(size_t)BHTOT * S_LEN * DH];
__device__ float g_o[(size_t)MROWS * DM];           // [b*2048+s][h*64+d]

// ---------------------------------------------------------------------------
// SGEMM: C = A @ B + bias.  BM=BN=128, BK=8, 256 threads, 8x8 micro-tile.
// MODE 0: C row-major (final projection, C = d_out)
// MODE 1: scatter into g_q/g_k/g_v per qkv layout (A = x, B = W_qkv)
// MODE 2: like MODE 0 but A is implicitly g_o (attention output)
// M,N,K are multiples of 128/128/8 for all our calls: no bounds checks.
// ---------------------------------------------------------------------------
template <int MODE>
__global__ __launch_bounds__(256) void sgemm_kernel(
    const float* __restrict__ A, const float* __restrict__ B,
    const float* __restrict__ bias, float* __restrict__ C,
    int M, int N, int K)
{
    __shared__ float As[8][128];   // transposed A tile
    __shared__ float Bs[8][128];

    const float* Aeff = (MODE == 2) ? g_o : A;

    int tid = threadIdx.x;
    int tx = tid & 15;         // 0..15 -> output cols tx*8..tx*8+7
    int ty = tid >> 4;         // 0..15 -> output rows ty*8..ty*8+7
    int bm = blockIdx.y * 128;
    int bn = blockIdx.x * 128;

    int aRow = tid >> 1;            // 0..127
    int aCol = (tid & 1) * 4;       // 0 or 4
    int bRow = tid >> 5;            // 0..7
    int bCol = (tid & 31) * 4;      // 0..124

    const float* Ap = Aeff + (size_t)(bm + aRow) * K + aCol;
    const float* Bp = B    + (size_t)bRow * N + bn + bCol;

    float acc[8][8];
    #pragma unroll
    for (int i = 0; i < 8; i++)
        #pragma unroll
        for (int j = 0; j < 8; j++) acc[i][j] = 0.0f;

    for (int k0 = 0; k0 < K; k0 += 8) {
        float4 av = *(const float4*)(Ap + k0);
        float4 bv = *(const float4*)(Bp + (size_t)k0 * N);
        As[aCol + 0][aRow] = av.x;
        As[aCol + 1][aRow] = av.y;
        As[aCol + 2][aRow] = av.z;
        As[aCol + 3][aRow] = av.w;
        *(float4*)&Bs[bRow][bCol] = bv;
        __syncthreads();

        #pragma unroll
        for (int kk = 0; kk < 8; kk++) {
            float a[8], b[8];
            #pragma unroll
            for (int i = 0; i < 4; i++) {
                float4 t = *(const float4*)&As[kk][ty * 8 + i * 4];
                a[i*4+0] = t.x; a[i*4+1] = t.y; a[i*4+2] = t.z; a[i*4+3] = t.w;
            }
            #pragma unroll
            for (int j = 0; j < 2; j++) {
                float4 t = *(const float4*)&Bs[kk][tx * 8 + j * 4];
                b[j*4+0] = t.x; b[j*4+1] = t.y; b[j*4+2] = t.z; b[j*4+3] = t.w;
            }
            #pragma unroll
            for (int i = 0; i < 8; i++)
                #pragma unroll
                for (int j = 0; j < 8; j++)
                    acc[i][j] += a[i] * b[j];
        }
        __syncthreads();
    }

    // Epilogue
    #pragma unroll
    for (int i = 0; i < 8; i++) {
        int m = bm + ty * 8 + i;
        #pragma unroll
        for (int j = 0; j < 8; j++) {
            int n = bn + tx * 8 + j;
            float val = acc[i][j] + bias[n];
            if (MODE == 1) {
                // n in [0,3072): which = n/1024, h = (n%1024)/64, d = n%64
                int which = n >> 10;
                int h = (n & 1023) >> 6;
                int d = n & 63;
                int b = m >> 11;       // m / 2048
                int s = m & 2047;
                size_t dst = (((size_t)(b * NHEAD + h)) * S_LEN + s) * DH + d;
                float* P = (which == 0) ? g_q : (which == 1) ? g_k : g_v;
                P[dst] = val;
            } else {
                C[(size_t)m * N + n] = val;
            }
        }
    }
}

// ---------------------------------------------------------------------------
// Causal flash attention (fp32, online softmax).
// Grid: (32 q-tiles of 64, 64 bh). Block: 256 threads (16x16).
// Br=64 queries, Bc=32 keys per inner tile.
// Thread (ty,tx): S rows ty*4..+3, S cols tx*2..+1; O rows ty*4..+3, cols tx*4..+3
// ---------------------------------------------------------------------------
__global__ __launch_bounds__(256) void attn_kernel()
{
    __shared__ float Qs[64][64];      // broadcast access: no pad needed
    __shared__ float Ks[32][65];      // padded: stride-130 access conflict-free
    __shared__ float Vs[32][64];      // float4 access along d
    __shared__ float Ps[64][33];      // padded

    int qt = blockIdx.x;   // 0..31
    int bh = blockIdx.y;   // 0..63
    int tid = threadIdx.x;
    int tx = tid & 15;
    int ty = tid >> 4;

    const float scale = 0.125f;  // 1/sqrt(64)
    const float* qbase = g_q + (size_t)bh * S_LEN * DH;
    const float* kbase = g_k + (size_t)bh * S_LEN * DH;
    const float* vbase = g_v + (size_t)bh * S_LEN * DH;

    // Load Q tile (64x64): 1024 float4s, 4 per thread
    #pragma unroll
    for (int it = 0; it < 4; it++) {
        int idx = tid + 256 * it;           // float4 index
        int r = idx >> 4;
        int c4 = (idx & 15) << 2;
        *(float4*)&Qs[r][c4] =
            *(const float4*)(qbase + (size_t)(qt * 64 + r) * DH + c4);
    }

    float m_i[4], l_i[4], o[4][4];
    #pragma unroll
    for (int i = 0; i < 4; i++) {
        m_i[i] = -INFINITY;
        l_i[i] = 0.0f;
        #pragma unroll
        for (int j = 0; j < 4; j++) o[i][j] = 0.0f;
    }

    int nkt = qt * 2 + 2;   // tiles of 32 keys covering [0, qt*64+63]
    for (int kt = 0; kt < nkt; kt++) {
        __syncthreads();    // previous iter's Ps/Vs reads done; Qs visible on kt=0
        // Load K,V tiles (32x64 each): 8 scalars per thread, coalesced
        #pragma unroll
        for (int it = 0; it < 8; it++) {
            int idx = tid + 256 * it;
            int c = idx >> 6;
            int d = idx & 63;
            size_t g = (size_t)(kt * 32 + c) * DH + d;
            Ks[c][d] = kbase[g];
            Vs[c][d] = vbase[g];
        }
        __syncthreads();

        // S = Q K^T  (thread: 4 rows x 2 cols)
        float s[4][2];
        #pragma unroll
        for (int i = 0; i < 4; i++) { s[i][0] = 0.0f; s[i][1] = 0.0f; }
        int r0 = ty * 4;
        int c0 = tx * 2;
        #pragma unroll 4
        for (int d = 0; d < 64; d++) {
            float k0v = Ks[c0 + 0][d];
            float k1v = Ks[c0 + 1][d];
            #pragma unroll
            for (int i = 0; i < 4; i++) {
                float qv = Qs[r0 + i][d];
                s[i][0] += qv * k0v;
                s[i][1] += qv * k1v;
            }
        }

        // scale + causal mask
        int qg0 = qt * 64 + r0;
        int kg0 = kt * 32 + c0;
        #pragma unroll
        for (int i = 0; i < 4; i++) {
            #pragma unroll
            for (int j = 0; j < 2; j++) {
                s[i][j] = (kg0 + j <= qg0 + i) ? s[i][j] * scale : -INFINITY;
            }
        }

        // online softmax update
        float alpha[4];
        #pragma unroll
        for (int i = 0; i < 4; i++) {
            float v = fmaxf(s[i][0], s[i][1]);
            #pragma unroll
            for (int off = 8; off >= 1; off >>= 1)
                v = fmaxf(v, __shfl_xor_sync(0xffffffffu, v, off));
            float mnew = fmaxf(m_i[i], v);
            alpha[i] = __expf(m_i[i] - mnew);     // 0 when m_i=-inf
            float p0 = __expf(s[i][0] - mnew);
            float p1 = __expf(s[i][1] - mnew);
            Ps[r0 + i][c0 + 0] = p0;
            Ps[r0 + i][c0 + 1] = p1;
            float ps = p0 + p1;
            #pragma unroll
            for (int off = 8; off >= 1; off >>= 1)
                ps += __shfl_xor_sync(0xffffffffu, ps, off);
            l_i[i] = l_i[i] * alpha[i] + ps;
            m_i[i] = mnew;
        }
        __syncthreads();

        // O = O*alpha + P @ V  (thread: 4 rows x 4 dims at tx*4)
        #pragma unroll
        for (int i = 0; i < 4; i++)
            #pragma unroll
            for (int j = 0; j < 4; j++) o[i][j] *= alpha[i];

        int d0 = tx * 4;
        #pragma unroll 4
        for (int c = 0; c < 32; c++) {
            float4 vv = *(const float4*)&Vs[c][d0];
            float vj[4] = {vv.x, vv.y, vv.z, vv.w};
            #pragma unroll
            for (int i = 0; i < 4; i++) {
                float pv = Ps[r0 + i][c];
                #pragma unroll
                for (int j = 0; j < 4; j++) o[i][j] += pv * vj[j];
            }
        }
    }

    // Epilogue: g_o[b*2048+s][h*64+d]
    int b = bh >> 4;
    int h = bh & 15;
    #pragma unroll
    for (int i = 0; i < 4; i++) {
        float inv = 1.0f / l_i[i];
        int srow = qt * 64 + ty * 4 + i;
        float* dst = g_o + ((size_t)(b * S_LEN + srow)) * DM + h * DH + tx * 4;
        float4 w;
        w.x = o[i][0] * inv;
        w.y = o[i][1] * inv;
        w.z = o[i][2] * inv;
        w.w = o[i][3] * inv;
        *(float4*)dst = w;
    }
}

// ---------------------------------------------------------------------------
extern "C" void kernel_launch(void* const* d_in, const int* in_sizes, int n_in,
                              void* d_out, int out_size)
{
    const float* x     = (const float*)d_in[0];   // (4,2048,1024)
    const float* W_qkv = (const float*)d_in[1];   // (1024,3072)
    const float* b_qkv = (const float*)d_in[2];   // (3072,)
    const float* W_out = (const float*)d_in[3];   // (1024,1024)
    const float* b_out = (const float*)d_in[4];   // (1024,)
    float* out = (float*)d_out;                   // (4,2048,1024)

    dim3 blk(256);

    // 1) QKV projection: (8192x1024) @ (1024x3072) -> scatter to g_q/g_k/g_v
    {
        dim3 grid(3 * DM / 128, MROWS / 128);     // (24, 64)
        sgemm_kernel<1><<<grid, blk>>>(x, W_qkv, b_qkv, nullptr,
                                       MROWS, 3 * DM, DM);
    }

    // 2) Causal flash attention -> g_o
    {
        dim3 grid(S_LEN / 64, BHTOT);             // (32, 64)
        attn_kernel<<<grid, blk>>>();
    }

    // 3) Output projection: g_o (8192x1024) @ (1024x1024) + b_out -> d_out
    {
        dim3 grid(DM / 128, MROWS / 128);         // (8, 64)
        sgemm_kernel<2><<<grid, blk>>>(nullptr, W_out, b_out, out,
                                       MROWS, DM, DM);
    }
}

// round 3
// speedup vs baseline: 1.8125x; 1.8125x over previous
#include <cuda_runtime.h>
#include <math.h>
#include <stdint.h>

// Problem constants
#define BATCH   4
#define S_LEN   2048
#define NHEAD   16
#define DH      64
#define DM      1024
#define BHTOT   (BATCH*NHEAD)   // 64
#define MROWS   (BATCH*S_LEN)   // 8192

// Scratch (device globals: allocation-free, graph-capturable)
__device__ float g_q[(size_t)BHTOT * S_LEN * DH];
__device__ float g_k[(size_t)BHTOT * S_LEN * DH];
__device__ float g_v[(size_t)BHTOT * S_LEN * DH];
__device__ float g_o[(size_t)MROWS * DM];
__device__ float g_wt[(size_t)3 * DM * DM];   // W_qkv^T : [3072][1024]
__device__ float g_wo[(size_t)DM * DM];       // W_out^T : [1024][1024]

// ---------------------------------------------------------------------------
__device__ __forceinline__ uint32_t f2tf32(float x) {
    uint32_t u;
    asm("cvt.rna.tf32.f32 %0, %1;" : "=r"(u) : "f"(x));
    return u;
}

__device__ __forceinline__ void mma_tf32(float* c, const uint32_t* a, const uint32_t* b) {
    asm volatile(
        "mma.sync.aligned.m16n8k8.row.col.f32.tf32.tf32.f32 "
        "{%0,%1,%2,%3}, {%4,%5,%6,%7}, {%8,%9}, {%0,%1,%2,%3};"
        : "+f"(c[0]), "+f"(c[1]), "+f"(c[2]), "+f"(c[3])
        : "r"(a[0]), "r"(a[1]), "r"(a[2]), "r"(a[3]), "r"(b[0]), "r"(b[1]));
}

// ---------------------------------------------------------------------------
// Transpose: out[c][r] = in[r][c].  in: [R][C].  block (32,8), grid (C/32, R/32)
// ---------------------------------------------------------------------------
__global__ void transpose_kernel(const float* __restrict__ in, float* __restrict__ out,
                                 int R, int C)
{
    __shared__ float t[32][33];
    int bx = blockIdx.x * 32, by = blockIdx.y * 32;
    int x = threadIdx.x, y0 = threadIdx.y;
    #pragma unroll
    for (int i = 0; i < 32; i += 8)
        t[y0 + i][x] = in[(size_t)(by + y0 + i) * C + bx + x];
    __syncthreads();
    #pragma unroll
    for (int i = 0; i < 32; i += 8)
        out[(size_t)(bx + y0 + i) * R + by + x] = t[x][y0 + i];
}

// ---------------------------------------------------------------------------
// tf32 mma.sync GEMM.  C[M,N] = A[M,K] @ B[N,K]^T + bias (both K-major).
// CTA tile 128x128, BK=16, 256 threads = 8 warps (2 M x 4 N), warp tile 64x32.
// Per warp: 4 m-tiles(16) x 4 n-tiles(8), k in steps of 8 -> m16n8k8 HMMA.
// SMEM m-major [row][k] stride 20 words: frag LDS conflict-free.
// MODE 1: A = x, B = g_wt (N=3072), scatter epilogue to g_q/g_k/g_v
// MODE 0: A = g_o, B = g_wo (N=1024), C = d_out
// K = 1024 fixed.
// ---------------------------------------------------------------------------
template <int MODE>
__global__ __launch_bounds__(256) void mma_gemm(
    const float* __restrict__ Ax, const float* __restrict__ bias,
    float* __restrict__ C)
{
    __shared__ uint32_t As[2][128][20];
    __shared__ uint32_t Bs[2][128][20];

    const float* Ag = (MODE == 1) ? Ax : g_o;
    const float* Bg = (MODE == 1) ? g_wt : g_wo;

    const int tid = threadIdx.x;
    const int lane = tid & 31;
    const int wid = tid >> 5;
    const int wm = wid & 1;          // 0..1 -> 64-row half
    const int wn = wid >> 1;         // 0..3 -> 32-col quarter
    const int bm = blockIdx.y * 128;
    const int bn = blockIdx.x * 128;

    const int lm = tid >> 2;         // 0..63
    const int lk = (tid & 3) * 4;    // 0,4,8,12

    const float* Arow0 = Ag + (size_t)(bm + lm) * 1024 + lk;
    const float* Arow1 = Ag + (size_t)(bm + lm + 64) * 1024 + lk;
    const float* Brow0 = Bg + (size_t)(bn + lm) * 1024 + lk;
    const float* Brow1 = Bg + (size_t)(bn + lm + 64) * 1024 + lk;

    float4 ra0, ra1, rb0, rb1;

    float acc[4][4][4];
    #pragma unroll
    for (int mt = 0; mt < 4; mt++)
        #pragma unroll
        for (int nt = 0; nt < 4; nt++)
            #pragma unroll
            for (int r = 0; r < 4; r++) acc[mt][nt][r] = 0.0f;

    const int grp = lane >> 2;       // 0..7
    const int q = lane & 3;          // 0..3

    // preload iter 0
    ra0 = *(const float4*)(Arow0);
    ra1 = *(const float4*)(Arow1);
    rb0 = *(const float4*)(Brow0);
    rb1 = *(const float4*)(Brow1);

    #pragma unroll 1
    for (int it = 0; it < 64; it++) {
        int cur = it & 1;
        // store prefetched chunk into buffer `cur`
        As[cur][lm][lk + 0] = f2tf32(ra0.x);
        As[cur][lm][lk + 1] = f2tf32(ra0.y);
        As[cur][lm][lk + 2] = f2tf32(ra0.z);
        As[cur][lm][lk + 3] = f2tf32(ra0.w);
        As[cur][lm + 64][lk + 0] = f2tf32(ra1.x);
        As[cur][lm + 64][lk + 1] = f2tf32(ra1.y);
        As[cur][lm + 64][lk + 2] = f2tf32(ra1.z);
        As[cur][lm + 64][lk + 3] = f2tf32(ra1.w);
        Bs[cur][lm][lk + 0] = f2tf32(rb0.x);
        Bs[cur][lm][lk + 1] = f2tf32(rb0.y);
        Bs[cur][lm][lk + 2] = f2tf32(rb0.z);
        Bs[cur][lm][lk + 3] = f2tf32(rb0.w);
        Bs[cur][lm + 64][lk + 0] = f2tf32(rb1.x);
        Bs[cur][lm + 64][lk + 1] = f2tf32(rb1.y);
        Bs[cur][lm + 64][lk + 2] = f2tf32(rb1.z);
        Bs[cur][lm + 64][lk + 3] = f2tf32(rb1.w);
        __syncthreads();

        // prefetch next chunk (global latency overlapped with compute)
        if (it < 63) {
            int k0 = (it + 1) * 16;
            ra0 = *(const float4*)(Arow0 + k0);
            ra1 = *(const float4*)(Arow1 + k0);
            rb0 = *(const float4*)(Brow0 + k0);
            rb1 = *(const float4*)(Brow1 + k0);
        }

        // compute on buffer `cur`
        #pragma unroll
        for (int ks = 0; ks < 16; ks += 8) {
            uint32_t afr[4][4];
            #pragma unroll
            for (int mt = 0; mt < 4; mt++) {
                int mrow = wm * 64 + mt * 16 + grp;
                afr[mt][0] = As[cur][mrow][ks + q];
                afr[mt][1] = As[cur][mrow + 8][ks + q];
                afr[mt][2] = As[cur][mrow][ks + q + 4];
                afr[mt][3] = As[cur][mrow + 8][ks + q + 4];
            }
            uint32_t bfr[4][2];
            #pragma unroll
            for (int nt = 0; nt < 4; nt++) {
                int ncol = wn * 32 + nt * 8 + grp;
                bfr[nt][0] = Bs[cur][ncol][ks + q];
                bfr[nt][1] = Bs[cur][ncol][ks + q + 4];
            }
            #pragma unroll
            for (int mt = 0; mt < 4; mt++)
                #pragma unroll
                for (int nt = 0; nt < 4; nt++)
                    mma_tf32(acc[mt][nt], afr[mt], bfr[nt]);
        }
        __syncthreads();   // all warps done reading `cur` before it is overwritten
    }

    // Epilogue: c0,c1 at (row, col..col+1); c2,c3 at (row+8, ...)
    #pragma unroll
    for (int mt = 0; mt < 4; mt++) {
        int r0 = bm + wm * 64 + mt * 16 + grp;
        #pragma unroll
        for (int nt = 0; nt < 4; nt++) {
            int col = bn + wn * 32 + nt * 8 + q * 2;
            float b0 = bias[col], b1 = bias[col + 1];
            float2 v0 = make_float2(acc[mt][nt][0] + b0, acc[mt][nt][1] + b1);
            float2 v1 = make_float2(acc[mt][nt][2] + b0, acc[mt][nt][3] + b1);
            if (MODE == 1) {
                int which = col >> 10;
                int h = (col & 1023) >> 6;
                int d = col & 63;
                float* P = (which == 0) ? g_q : (which == 1) ? g_k : g_v;
                int b_0 = r0 >> 11, s0 = r0 & 2047;
                *(float2*)(P + (((size_t)(b_0 * NHEAD + h)) * S_LEN + s0) * DH + d) = v0;
                int r1 = r0 + 8;
                int b_1 = r1 >> 11, s1 = r1 & 2047;
                *(float2*)(P + (((size_t)(b_1 * NHEAD + h)) * S_LEN + s1) * DH + d) = v1;
            } else {
                *(float2*)(C + (size_t)r0 * DM + col) = v0;
                *(float2*)(C + (size_t)(r0 + 8) * DM + col) = v1;
            }
        }
    }
}

// ---------------------------------------------------------------------------
// Causal flash attention (fp32, online softmax) — unchanged from R1.
// ---------------------------------------------------------------------------
__global__ __launch_bounds__(256) void attn_kernel()
{
    __shared__ float Qs[64][64];
    __shared__ float Ks[32][65];
    __shared__ float Vs[32][64];
    __shared__ float Ps[64][33];

    int qt = blockIdx.x;
    int bh = blockIdx.y;
    int tid = threadIdx.x;
    int tx = tid & 15;
    int ty = tid >> 4;

    const float scale = 0.125f;
    const float* qbase = g_q + (size_t)bh * S_LEN * DH;
    const float* kbase = g_k + (size_t)bh * S_LEN * DH;
    const float* vbase = g_v + (size_t)bh * S_LEN * DH;

    #pragma unroll
    for (int it = 0; it < 4; it++) {
        int idx = tid + 256 * it;
        int r = idx >> 4;
        int c4 = (idx & 15) << 2;
        *(float4*)&Qs[r][c4] =
            *(const float4*)(qbase + (size_t)(qt * 64 + r) * DH + c4);
    }

    float m_i[4], l_i[4], o[4][4];
    #pragma unroll
    for (int i = 0; i < 4; i++) {
        m_i[i] = -INFINITY;
        l_i[i] = 0.0f;
        #pragma unroll
        for (int j = 0; j < 4; j++) o[i][j] = 0.0f;
    }

    int nkt = qt * 2 + 2;
    for (int kt = 0; kt < nkt; kt++) {
        __syncthreads();
        #pragma unroll
        for (int it = 0; it < 8; it++) {
            int idx = tid + 256 * it;
            int c = idx >> 6;
            int d = idx & 63;
            size_t g = (size_t)(kt * 32 + c) * DH + d;
            Ks[c][d] = kbase[g];
            Vs[c][d] = vbase[g];
        }
        __syncthreads();

        float s[4][2];
        #pragma unroll
        for (int i = 0; i < 4; i++) { s[i][0] = 0.0f; s[i][1] = 0.0f; }
        int r0 = ty * 4;
        int c0 = tx * 2;
        #pragma unroll 4
        for (int d = 0; d < 64; d++) {
            float k0v = Ks[c0 + 0][d];
            float k1v = Ks[c0 + 1][d];
            #pragma unroll
            for (int i = 0; i < 4; i++) {
                float qv = Qs[r0 + i][d];
                s[i][0] += qv * k0v;
                s[i][1] += qv * k1v;
            }
        }

        int qg0 = qt * 64 + r0;
        int kg0 = kt * 32 + c0;
        #pragma unroll
        for (int i = 0; i < 4; i++) {
            #pragma unroll
            for (int j = 0; j < 2; j++) {
                s[i][j] = (kg0 + j <= qg0 + i) ? s[i][j] * scale : -INFINITY;
            }
        }

        float alpha[4];
        #pragma unroll
        for (int i = 0; i < 4; i++) {
            float v = fmaxf(s[i][0], s[i][1]);
            #pragma unroll
            for (int off = 8; off >= 1; off >>= 1)
                v = fmaxf(v, __shfl_xor_sync(0xffffffffu, v, off));
            float mnew = fmaxf(m_i[i], v);
            alpha[i] = __expf(m_i[i] - mnew);
            float p0 = __expf(s[i][0] - mnew);
            float p1 = __expf(s[i][1] - mnew);
            Ps[r0 + i][c0 + 0] = p0;
            Ps[r0 + i][c0 + 1] = p1;
            float ps = p0 + p1;
            #pragma unroll
            for (int off = 8; off >= 1; off >>= 1)
                ps += __shfl_xor_sync(0xffffffffu, ps, off);
            l_i[i] = l_i[i] * alpha[i] + ps;
            m_i[i] = mnew;
        }
        __syncthreads();

        #pragma unroll
        for (int i = 0; i < 4; i++)
            #pragma unroll
            for (int j = 0; j < 4; j++) o[i][j] *= alpha[i];

        int d0 = tx * 4;
        #pragma unroll 4
        for (int c = 0; c < 32; c++) {
            float4 vv = *(const float4*)&Vs[c][d0];
            float vj[4] = {vv.x, vv.y, vv.z, vv.w};
            #pragma unroll
            for (int i = 0; i < 4; i++) {
                float pv = Ps[r0 + i][c];
                #pragma unroll
                for (int j = 0; j < 4; j++) o[i][j] += pv * vj[j];
            }
        }
    }

    int b = bh >> 4;
    int h = bh & 15;
    #pragma unroll
    for (int i = 0; i < 4; i++) {
        float inv = 1.0f / l_i[i];
        int srow = qt * 64 + ty * 4 + i;
        float* dst = g_o + ((size_t)(b * S_LEN + srow)) * DM + h * DH + tx * 4;
        float4 w;
        w.x = o[i][0] * inv;
        w.y = o[i][1] * inv;
        w.z = o[i][2] * inv;
        w.w = o[i][3] * inv;
        *(float4*)dst = w;
    }
}

// ---------------------------------------------------------------------------
extern "C" void kernel_launch(void* const* d_in, const int* in_sizes, int n_in,
                              void* d_out, int out_size)
{
    const float* x     = (const float*)d_in[0];
    const float* W_qkv = (const float*)d_in[1];
    const float* b_qkv = (const float*)d_in[2];
    const float* W_out = (const float*)d_in[3];
    const float* b_out = (const float*)d_in[4];
    float* out = (float*)d_out;

    float* wt;  cudaGetSymbolAddress((void**)&wt, g_wt);
    float* wo;  cudaGetSymbolAddress((void**)&wo, g_wo);

    // 0) Transpose weights to K-major
    {
        dim3 blk(32, 8);
        transpose_kernel<<<dim3(3 * DM / 32, DM / 32), blk>>>(W_qkv, wt, DM, 3 * DM);
        transpose_kernel<<<dim3(DM / 32, DM / 32), blk>>>(W_out, wo, DM, DM);
    }

    // 1) QKV projection (tf32 mma.sync) -> scatter to g_q/g_k/g_v
    {
        dim3 grid(3 * DM / 128, MROWS / 128);   // (24, 64)
        mma_gemm<1><<<grid, 256>>>(x, b_qkv, nullptr);
    }

    // 2) Causal flash attention -> g_o
    {
        dim3 grid(S_LEN / 64, BHTOT);           // (32, 64)
        attn_kernel<<<grid, 256>>>();
    }

    // 3) Output projection (tf32 mma.sync) -> d_out
    {
        dim3 grid(DM / 128, MROWS / 128);       // (8, 64)
        mma_gemm<0><<<grid, 256>>>(nullptr, b_out, out);
    }
}

// round 4
// speedup vs baseline: 3.6030x; 1.9879x over previous
#include <cuda_runtime.h>
#include <math.h>
#include <stdint.h>

// Problem constants
#define BATCH   4
#define S_LEN   2048
#define NHEAD   16
#define DH      64
#define DM      1024
#define BHTOT   (BATCH*NHEAD)   // 64
#define MROWS   (BATCH*S_LEN)   // 8192

// Scratch (device globals: allocation-free, graph-capturable)
__device__ float g_q[(size_t)BHTOT * S_LEN * DH];
__device__ float g_k[(size_t)BHTOT * S_LEN * DH];
__device__ float g_v[(size_t)BHTOT * S_LEN * DH];
__device__ float g_o[(size_t)MROWS * DM];
__device__ float g_wt[(size_t)3 * DM * DM];   // W_qkv^T : [3072][1024]
__device__ float g_wo[(size_t)DM * DM];       // W_out^T : [1024][1024]

// ---------------------------------------------------------------------------
__device__ __forceinline__ uint32_t f2tf32(float x) {
    uint32_t u;
    asm("cvt.rna.tf32.f32 %0, %1;" : "=r"(u) : "f"(x));
    return u;
}

__device__ __forceinline__ void mma_tf32(float* c, const uint32_t* a, const uint32_t* b) {
    asm volatile(
        "mma.sync.aligned.m16n8k8.row.col.f32.tf32.tf32.f32 "
        "{%0,%1,%2,%3}, {%4,%5,%6,%7}, {%8,%9}, {%0,%1,%2,%3};"
        : "+f"(c[0]), "+f"(c[1]), "+f"(c[2]), "+f"(c[3])
        : "r"(a[0]), "r"(a[1]), "r"(a[2]), "r"(a[3]), "r"(b[0]), "r"(b[1]));
}

// ---------------------------------------------------------------------------
// Transpose: out[c][r] = in[r][c].  in: [R][C].  block (32,8), grid (C/32, R/32)
// ---------------------------------------------------------------------------
__global__ void transpose_kernel(const float* __restrict__ in, float* __restrict__ out,
                                 int R, int C)
{
    __shared__ float t[32][33];
    int bx = blockIdx.x * 32, by = blockIdx.y * 32;
    int x = threadIdx.x, y0 = threadIdx.y;
    #pragma unroll
    for (int i = 0; i < 32; i += 8)
        t[y0 + i][x] = in[(size_t)(by + y0 + i) * C + bx + x];
    __syncthreads();
    #pragma unroll
    for (int i = 0; i < 32; i += 8)
        out[(size_t)(bx + y0 + i) * R + by + x] = t[x][y0 + i];
}

// ---------------------------------------------------------------------------
// tf32 mma.sync GEMM (unchanged from R3).
// ---------------------------------------------------------------------------
template <int MODE>
__global__ __launch_bounds__(256) void mma_gemm(
    const float* __restrict__ Ax, const float* __restrict__ bias,
    float* __restrict__ C)
{
    __shared__ uint32_t As[2][128][20];
    __shared__ uint32_t Bs[2][128][20];

    const float* Ag = (MODE == 1) ? Ax : g_o;
    const float* Bg = (MODE == 1) ? g_wt : g_wo;

    const int tid = threadIdx.x;
    const int lane = tid & 31;
    const int wid = tid >> 5;
    const int wm = wid & 1;
    const int wn = wid >> 1;
    const int bm = blockIdx.y * 128;
    const int bn = blockIdx.x * 128;

    const int lm = tid >> 2;
    const int lk = (tid & 3) * 4;

    const float* Arow0 = Ag + (size_t)(bm + lm) * 1024 + lk;
    const float* Arow1 = Ag + (size_t)(bm + lm + 64) * 1024 + lk;
    const float* Brow0 = Bg + (size_t)(bn + lm) * 1024 + lk;
    const float* Brow1 = Bg + (size_t)(bn + lm + 64) * 1024 + lk;

    float4 ra0, ra1, rb0, rb1;

    float acc[4][4][4];
    #pragma unroll
    for (int mt = 0; mt < 4; mt++)
        #pragma unroll
        for (int nt = 0; nt < 4; nt++)
            #pragma unroll
            for (int r = 0; r < 4; r++) acc[mt][nt][r] = 0.0f;

    const int grp = lane >> 2;
    const int q = lane & 3;

    ra0 = *(const float4*)(Arow0);
    ra1 = *(const float4*)(Arow1);
    rb0 = *(const float4*)(Brow0);
    rb1 = *(const float4*)(Brow1);

    #pragma unroll 1
    for (int it = 0; it < 64; it++) {
        int cur = it & 1;
        As[cur][lm][lk + 0] = f2tf32(ra0.x);
        As[cur][lm][lk + 1] = f2tf32(ra0.y);
        As[cur][lm][lk + 2] = f2tf32(ra0.z);
        As[cur][lm][lk + 3] = f2tf32(ra0.w);
        As[cur][lm + 64][lk + 0] = f2tf32(ra1.x);
        As[cur][lm + 64][lk + 1] = f2tf32(ra1.y);
        As[cur][lm + 64][lk + 2] = f2tf32(ra1.z);
        As[cur][lm + 64][lk + 3] = f2tf32(ra1.w);
        Bs[cur][lm][lk + 0] = f2tf32(rb0.x);
        Bs[cur][lm][lk + 1] = f2tf32(rb0.y);
        Bs[cur][lm][lk + 2] = f2tf32(rb0.z);
        Bs[cur][lm][lk + 3] = f2tf32(rb0.w);
        Bs[cur][lm + 64][lk + 0] = f2tf32(rb1.x);
        Bs[cur][lm + 64][lk + 1] = f2tf32(rb1.y);
        Bs[cur][lm + 64][lk + 2] = f2tf32(rb1.z);
        Bs[cur][lm + 64][lk + 3] = f2tf32(rb1.w);
        __syncthreads();

        if (it < 63) {
            int k0 = (it + 1) * 16;
            ra0 = *(const float4*)(Arow0 + k0);
            ra1 = *(const float4*)(Arow1 + k0);
            rb0 = *(const float4*)(Brow0 + k0);
            rb1 = *(const float4*)(Brow1 + k0);
        }

        #pragma unroll
        for (int ks = 0; ks < 16; ks += 8) {
            uint32_t afr[4][4];
            #pragma unroll
            for (int mt = 0; mt < 4; mt++) {
                int mrow = wm * 64 + mt * 16 + grp;
                afr[mt][0] = As[cur][mrow][ks + q];
                afr[mt][1] = As[cur][mrow + 8][ks + q];
                afr[mt][2] = As[cur][mrow][ks + q + 4];
                afr[mt][3] = As[cur][mrow + 8][ks + q + 4];
            }
            uint32_t bfr[4][2];
            #pragma unroll
            for (int nt = 0; nt < 4; nt++) {
                int ncol = wn * 32 + nt * 8 + grp;
                bfr[nt][0] = Bs[cur][ncol][ks + q];
                bfr[nt][1] = Bs[cur][ncol][ks + q + 4];
            }
            #pragma unroll
            for (int mt = 0; mt < 4; mt++)
                #pragma unroll
                for (int nt = 0; nt < 4; nt++)
                    mma_tf32(acc[mt][nt], afr[mt], bfr[nt]);
        }
        __syncthreads();
    }

    #pragma unroll
    for (int mt = 0; mt < 4; mt++) {
        int r0 = bm + wm * 64 + mt * 16 + grp;
        #pragma unroll
        for (int nt = 0; nt < 4; nt++) {
            int col = bn + wn * 32 + nt * 8 + q * 2;
            float b0 = bias[col], b1 = bias[col + 1];
            float2 v0 = make_float2(acc[mt][nt][0] + b0, acc[mt][nt][1] + b1);
            float2 v1 = make_float2(acc[mt][nt][2] + b0, acc[mt][nt][3] + b1);
            if (MODE == 1) {
                int which = col >> 10;
                int h = (col & 1023) >> 6;
                int d = col & 63;
                float* P = (which == 0) ? g_q : (which == 1) ? g_k : g_v;
                int b_0 = r0 >> 11, s0 = r0 & 2047;
                *(float2*)(P + (((size_t)(b_0 * NHEAD + h)) * S_LEN + s0) * DH + d) = v0;
                int r1 = r0 + 8;
                int b_1 = r1 >> 11, s1 = r1 & 2047;
                *(float2*)(P + (((size_t)(b_1 * NHEAD + h)) * S_LEN + s1) * DH + d) = v1;
            } else {
                *(float2*)(C + (size_t)r0 * DM + col) = v0;
                *(float2*)(C + (size_t)(r0 + 8) * DM + col) = v1;
            }
        }
    }
}

// ---------------------------------------------------------------------------
// Tensorized causal flash attention (tf32 mma.sync, online softmax).
// CTA: 128 q-rows (8 warps x 16 rows), key tiles of 64, Dh = 64.
// SMEM: Pbuf[128][68] (Q staging, then P), Ks[64][68], Vs[64][72].
// Grid: (16 qt, 64 bh), heavy qt first. Block: 256.
// ---------------------------------------------------------------------------
#define PB_STRIDE 68
#define KS_STRIDE 68
#define VS_STRIDE 72
#define ATT_SMEM ((128*PB_STRIDE + 64*KS_STRIDE + 64*VS_STRIDE) * 4)  // 70656 B

__global__ __launch_bounds__(256) void attn_mma_kernel()
{
    extern __shared__ uint32_t sm[];
    uint32_t (*Pbuf)[PB_STRIDE] = (uint32_t(*)[PB_STRIDE])sm;
    uint32_t (*Ks)[KS_STRIDE]   = (uint32_t(*)[KS_STRIDE])(sm + 128 * PB_STRIDE);
    uint32_t (*Vs)[VS_STRIDE]   = (uint32_t(*)[VS_STRIDE])(sm + 128 * PB_STRIDE + 64 * KS_STRIDE);

    const int qt = (int)gridDim.x - 1 - (int)blockIdx.x;   // heavy CTAs first
    const int bh = blockIdx.y;
    const int tid = threadIdx.x;
    const int lane = tid & 31;
    const int w = tid >> 5;          // warp 0..7 -> rows w*16..w*16+15
    const int grp = lane >> 2;       // 0..7
    const int q = lane & 3;          // 0..3

    const float scale = 0.125f;      // 1/sqrt(64), exact power of two
    const float* qb = g_q + (size_t)bh * S_LEN * DH + (size_t)qt * 128 * DH;
    const float* kb = g_k + (size_t)bh * S_LEN * DH;
    const float* vb = g_v + (size_t)bh * S_LEN * DH;

    // Stage Q (scaled, tf32) then pick up per-warp A fragments into registers.
    #pragma unroll
    for (int i = 0; i < 8; i++) {
        int idx = tid + 256 * i;         // float4 index over 128x16
        int r = idx >> 4;
        int c4 = (idx & 15) << 2;
        float4 v = *(const float4*)(qb + (size_t)r * DH + c4);
        Pbuf[r][c4 + 0] = f2tf32(v.x * scale);
        Pbuf[r][c4 + 1] = f2tf32(v.y * scale);
        Pbuf[r][c4 + 2] = f2tf32(v.z * scale);
        Pbuf[r][c4 + 3] = f2tf32(v.w * scale);
    }
    __syncthreads();

    uint32_t aq[8][4];
    {
        int r0 = w * 16 + grp;
        #pragma unroll
        for (int ks = 0; ks < 8; ks++) {
            aq[ks][0] = Pbuf[r0][ks * 8 + q];
            aq[ks][1] = Pbuf[r0 + 8][ks * 8 + q];
            aq[ks][2] = Pbuf[r0][ks * 8 + q + 4];
            aq[ks][3] = Pbuf[r0 + 8][ks * 8 + q + 4];
        }
    }

    const int row0g = qt * 128 + w * 16 + grp;   // global q row of c0/c1
    const int row1g = row0g + 8;                 // global q row of c2/c3

    float m0 = -INFINITY, m1 = -INFINITY;
    float l0 = 0.0f, l1 = 0.0f;
    float ao[8][4];
    #pragma unroll
    for (int nt = 0; nt < 8; nt++)
        #pragma unroll
        for (int r = 0; r < 4; r++) ao[nt][r] = 0.0f;

    const int nkt = 2 * qt + 2;
    #pragma unroll 1
    for (int kt = 0; kt < nkt; kt++) {
        __syncthreads();   // Ks/Vs (and Pbuf) free from previous iteration
        // Load K,V tile (64x64 each) -> tf32 SMEM
        #pragma unroll
        for (int i = 0; i < 4; i++) {
            int idx = tid + 256 * i;     // float4 index over 64x16
            int r = idx >> 4;
            int c4 = (idx & 15) << 2;
            size_t g = (size_t)(kt * 64 + r) * DH + c4;
            float4 kv = *(const float4*)(kb + g);
            float4 vv = *(const float4*)(vb + g);
            Ks[r][c4 + 0] = f2tf32(kv.x);
            Ks[r][c4 + 1] = f2tf32(kv.y);
            Ks[r][c4 + 2] = f2tf32(kv.z);
            Ks[r][c4 + 3] = f2tf32(kv.w);
            Vs[r][c4 + 0] = f2tf32(vv.x);
            Vs[r][c4 + 1] = f2tf32(vv.y);
            Vs[r][c4 + 2] = f2tf32(vv.z);
            Vs[r][c4 + 3] = f2tf32(vv.w);
        }
        __syncthreads();

        // S = (Q*scale) K^T : 8 n-tiles x 8 k-steps
        float sacc[8][4];
        #pragma unroll
        for (int nt = 0; nt < 8; nt++) {
            sacc[nt][0] = 0.0f; sacc[nt][1] = 0.0f;
            sacc[nt][2] = 0.0f; sacc[nt][3] = 0.0f;
        }
        #pragma unroll
        for (int ks = 0; ks < 8; ks++) {
            #pragma unroll
            for (int nt = 0; nt < 8; nt++) {
                uint32_t bfr[2];
                bfr[0] = Ks[nt * 8 + grp][ks * 8 + q];
                bfr[1] = Ks[nt * 8 + grp][ks * 8 + q + 4];
                mma_tf32(sacc[nt], aq[ks], bfr);
            }
        }

        // Causal mask (diagonal tiles only)
        if (kt >= 2 * qt) {
            #pragma unroll
            for (int nt = 0; nt < 8; nt++) {
                int c0g = kt * 64 + nt * 8 + 2 * q;
                if (c0g     > row0g) sacc[nt][0] = -INFINITY;
                if (c0g + 1 > row0g) sacc[nt][1] = -INFINITY;
                if (c0g     > row1g) sacc[nt][2] = -INFINITY;
                if (c0g + 1 > row1g) sacc[nt][3] = -INFINITY;
            }
        }

        // Online softmax
        float mt0 = -INFINITY, mt1 = -INFINITY;
        #pragma unroll
        for (int nt = 0; nt < 8; nt++) {
            mt0 = fmaxf(mt0, fmaxf(sacc[nt][0], sacc[nt][1]));
            mt1 = fmaxf(mt1, fmaxf(sacc[nt][2], sacc[nt][3]));
        }
        mt0 = fmaxf(mt0, __shfl_xor_sync(0xffffffffu, mt0, 1));
        mt0 = fmaxf(mt0, __shfl_xor_sync(0xffffffffu, mt0, 2));
        mt1 = fmaxf(mt1, __shfl_xor_sync(0xffffffffu, mt1, 1));
        mt1 = fmaxf(mt1, __shfl_xor_sync(0xffffffffu, mt1, 2));

        float mn0 = fmaxf(m0, mt0);
        float mn1 = fmaxf(m1, mt1);
        float al0 = __expf(m0 - mn0);
        float al1 = __expf(m1 - mn1);

        float rs0 = 0.0f, rs1 = 0.0f;
        int pr0 = w * 16 + grp;
        #pragma unroll
        for (int nt = 0; nt < 8; nt++) {
            float p0 = __expf(sacc[nt][0] - mn0);
            float p1 = __expf(sacc[nt][1] - mn0);
            float p2 = __expf(sacc[nt][2] - mn1);
            float p3 = __expf(sacc[nt][3] - mn1);
            rs0 += p0 + p1;
            rs1 += p2 + p3;
            Pbuf[pr0][nt * 8 + 2 * q]     = f2tf32(p0);
            Pbuf[pr0][nt * 8 + 2 * q + 1] = f2tf32(p1);
            Pbuf[pr0 + 8][nt * 8 + 2 * q]     = f2tf32(p2);
            Pbuf[pr0 + 8][nt * 8 + 2 * q + 1] = f2tf32(p3);
        }
        rs0 += __shfl_xor_sync(0xffffffffu, rs0, 1);
        rs0 += __shfl_xor_sync(0xffffffffu, rs0, 2);
        rs1 += __shfl_xor_sync(0xffffffffu, rs1, 1);
        rs1 += __shfl_xor_sync(0xffffffffu, rs1, 2);

        l0 = l0 * al0 + rs0;
        l1 = l1 * al1 + rs1;
        m0 = mn0;
        m1 = mn1;

        // Rescale O
        #pragma unroll
        for (int nt = 0; nt < 8; nt++) {
            ao[nt][0] *= al0; ao[nt][1] *= al0;
            ao[nt][2] *= al1; ao[nt][3] *= al1;
        }

        __syncwarp();   // P staging is warp-local (same rows written & read)

        // O += P @ V : 8 k-steps x 8 n-tiles (n = head dim)
        #pragma unroll
        for (int ks = 0; ks < 8; ks++) {
            uint32_t ap[4];
            ap[0] = Pbuf[pr0][ks * 8 + q];
            ap[1] = Pbuf[pr0 + 8][ks * 8 + q];
            ap[2] = Pbuf[pr0][ks * 8 + q + 4];
            ap[3] = Pbuf[pr0 + 8][ks * 8 + q + 4];
            #pragma unroll
            for (int nt = 0; nt < 8; nt++) {
                uint32_t bfr[2];
                bfr[0] = Vs[ks * 8 + q][nt * 8 + grp];
                bfr[1] = Vs[ks * 8 + q + 4][nt * 8 + grp];
                mma_tf32(ao[nt], ap, bfr);
            }
        }
        __syncwarp();   // done reading Pbuf before next-iter rewrite barrier
    }

    // Epilogue -> g_o[b*2048+s][h*64+d]
    float inv0 = 1.0f / l0;
    float inv1 = 1.0f / l1;
    int b = bh >> 4;
    int h = bh & 15;
    float* o0 = g_o + ((size_t)(b * S_LEN + row0g)) * DM + h * DH;
    float* o1 = g_o + ((size_t)(b * S_LEN + row1g)) * DM + h * DH;
    #pragma unroll
    for (int nt = 0; nt < 8; nt++) {
        int col = nt * 8 + 2 * q;
        *(float2*)(o0 + col) = make_float2(ao[nt][0] * inv0, ao[nt][1] * inv0);
        *(float2*)(o1 + col) = make_float2(ao[nt][2] * inv1, ao[nt][3] * inv1);
    }
}

// ---------------------------------------------------------------------------
extern "C" void kernel_launch(void* const* d_in, const int* in_sizes, int n_in,
                              void* d_out, int out_size)
{
    const float* x     = (const float*)d_in[0];
    const float* W_qkv = (const float*)d_in[2 - 1];   // d_in[1]
    const float* b_qkv = (const float*)d_in[2];
    const float* W_out = (const float*)d_in[3];
    const float* b_out = (const float*)d_in[4];
    float* out = (float*)d_out;

    cudaFuncSetAttribute(attn_mma_kernel,
                         cudaFuncAttributeMaxDynamicSharedMemorySize, ATT_SMEM);

    float* wt;  cudaGetSymbolAddress((void**)&wt, g_wt);
    float* wo;  cudaGetSymbolAddress((void**)&wo, g_wo);

    // 0) Transpose weights to K-major
    {
        dim3 blk(32, 8);
        transpose_kernel<<<dim3(3 * DM / 32, DM / 32), blk>>>(W_qkv, wt, DM, 3 * DM);
        transpose_kernel<<<dim3(DM / 32, DM / 32), blk>>>(W_out, wo, DM, DM);
    }

    // 1) QKV projection (tf32 mma.sync) -> scatter to g_q/g_k/g_v
    {
        dim3 grid(3 * DM / 128, MROWS / 128);   // (24, 64)
        mma_gemm<1><<<grid, 256>>>(x, b_qkv, nullptr);
    }

    // 2) Tensorized causal flash attention -> g_o
    {
        dim3 grid(S_LEN / 128, BHTOT);          // (16, 64)
        attn_mma_kernel<<<grid, 256, ATT_SMEM>>>();
    }

    // 3) Output projection (tf32 mma.sync) -> d_out
    {
        dim3 grid(DM / 128, MROWS / 128);       // (8, 64)
        mma_gemm<0><<<grid, 256>>>(nullptr, b_out, out);
    }
}

// round 5
// speedup vs baseline: 3.8006x; 1.0548x over previous
#include <cuda_runtime.h>
#include <math.h>
#include <stdint.h>

// Problem constants
#define BATCH   4
#define S_LEN   2048
#define NHEAD   16
#define DH      64
#define DM      1024
#define BHTOT   (BATCH*NHEAD)   // 64
#define MROWS   (BATCH*S_LEN)   // 8192

// Scratch (device globals: allocation-free, graph-capturable)
__device__ float g_q[(size_t)BHTOT * S_LEN * DH];
__device__ float g_k[(size_t)BHTOT * S_LEN * DH];
__device__ float g_v[(size_t)BHTOT * S_LEN * DH];
__device__ float g_o[(size_t)MROWS * DM];
__device__ uint32_t g_wt[(size_t)3 * DM * DM];   // W_qkv^T as tf32 bits : [3072][1024]
__device__ uint32_t g_wo[(size_t)DM * DM];       // W_out^T as tf32 bits : [1024][1024]

// ---------------------------------------------------------------------------
__device__ __forceinline__ uint32_t f2tf32(float x) {
    uint32_t u;
    asm("cvt.rna.tf32.f32 %0, %1;" : "=r"(u) : "f"(x));
    return u;
}

__device__ __forceinline__ void mma_tf32(float* c, const uint32_t* a, const uint32_t* b) {
    asm volatile(
        "mma.sync.aligned.m16n8k8.row.col.f32.tf32.tf32.f32 "
        "{%0,%1,%2,%3}, {%4,%5,%6,%7}, {%8,%9}, {%0,%1,%2,%3};"
        : "+f"(c[0]), "+f"(c[1]), "+f"(c[2]), "+f"(c[3])
        : "r"(a[0]), "r"(a[1]), "r"(a[2]), "r"(a[3]), "r"(b[0]), "r"(b[1]));
}

__device__ __forceinline__ void ldsm4(uint32_t* r, uint32_t addr) {
    asm volatile("ldmatrix.sync.aligned.m8n8.x4.shared.b16 {%0,%1,%2,%3}, [%4];"
                 : "=r"(r[0]), "=r"(r[1]), "=r"(r[2]), "=r"(r[3]) : "r"(addr));
}

__device__ __forceinline__ uint32_t smem_u32(const void* p) {
    uint32_t a;
    asm("{ .reg .u64 t; cvta.to.shared.u64 t, %1; cvt.u32.u64 %0, t; }"
        : "=r"(a) : "l"(p));
    return a;
}

// ---------------------------------------------------------------------------
// Transpose + tf32-convert: out[c][r] = tf32(in[r][c]).  in: [R][C].
// block (32,8), grid (C/32, R/32)
// ---------------------------------------------------------------------------
__global__ void transpose_tf32_kernel(const float* __restrict__ in,
                                      uint32_t* __restrict__ out, int R, int C)
{
    __shared__ float t[32][33];
    int bx = blockIdx.x * 32, by = blockIdx.y * 32;
    int x = threadIdx.x, y0 = threadIdx.y;
    #pragma unroll
    for (int i = 0; i < 32; i += 8)
        t[y0 + i][x] = in[(size_t)(by + y0 + i) * C + bx + x];
    __syncthreads();
    #pragma unroll
    for (int i = 0; i < 32; i += 8)
        out[(size_t)(bx + y0 + i) * R + by + x] = f2tf32(t[x][y0 + i]);
}

// ---------------------------------------------------------------------------
// tf32 mma.sync GEMM.  C[M,N] = A[M,K] @ B[N,K]^T + bias (both K-major).
// CTA tile 128x128, BK=16, 256 threads = 8 warps (2 M x 4 N), warp tile 64x32.
// Fragments via ldmatrix.x4 (conflict-free at stride 20).  B pre-tf32.
// MODE 1: A = x, B = g_wt (N=3072), scatter epilogue to g_q/g_k/g_v
// MODE 0: A = g_o, B = g_wo (N=1024), C = d_out
// ---------------------------------------------------------------------------
#define GSTR 20                      // smem row stride in words
#define GBUF (128*GSTR*4)            // bytes per buffer

template <int MODE>
__global__ __launch_bounds__(256, 2) void mma_gemm(
    const float* __restrict__ Ax, const float* __restrict__ bias,
    float* __restrict__ C)
{
    __shared__ uint32_t As[2][128][GSTR];
    __shared__ uint32_t Bs[2][128][GSTR];

    const float* Ag = (MODE == 1) ? Ax : g_o;
    const uint32_t* Bg = (MODE == 1) ? g_wt : g_wo;

    const int tid = threadIdx.x;
    const int lane = tid & 31;
    const int wid = tid >> 5;
    const int wm = wid & 1;
    const int wn = wid >> 1;
    const int bm = blockIdx.y * 128;
    const int bn = blockIdx.x * 128;

    const int lm = tid >> 2;
    const int lk = (tid & 3) * 4;

    const float* Arow0 = Ag + (size_t)(bm + lm) * 1024 + lk;
    const float* Arow1 = Ag + (size_t)(bm + lm + 64) * 1024 + lk;
    const uint32_t* Brow0 = Bg + (size_t)(bn + lm) * 1024 + lk;
    const uint32_t* Brow1 = Bg + (size_t)(bn + lm + 64) * 1024 + lk;

    const uint32_t as_u = smem_u32(&As[0][0][0]);
    const uint32_t bs_u = smem_u32(&Bs[0][0][0]);
    // ldmatrix per-lane offsets (bytes)
    const uint32_t a_inv = ((((lane >> 3) & 1) * 8 + (lane & 7)) * GSTR
                            + (((lane >> 4) & 1) << 2)) * 4;
    const uint32_t b_inv = ((((lane >> 4) & 1) * 8 + (lane & 7)) * GSTR
                            + (((lane >> 3) & 1) << 2)) * 4;

    float4 ra0, ra1;
    uint4 rb0, rb1;

    float acc[4][4][4];
    #pragma unroll
    for (int mt = 0; mt < 4; mt++)
        #pragma unroll
        for (int nt = 0; nt < 4; nt++)
            #pragma unroll
            for (int r = 0; r < 4; r++) acc[mt][nt][r] = 0.0f;

    const int grp = lane >> 2;
    const int q = lane & 3;

    ra0 = *(const float4*)(Arow0);
    ra1 = *(const float4*)(Arow1);
    rb0 = *(const uint4*)(Brow0);
    rb1 = *(const uint4*)(Brow1);

    #pragma unroll 1
    for (int it = 0; it < 64; it++) {
        int cur = it & 1;
        uint4 ua0 = make_uint4(f2tf32(ra0.x), f2tf32(ra0.y), f2tf32(ra0.z), f2tf32(ra0.w));
        uint4 ua1 = make_uint4(f2tf32(ra1.x), f2tf32(ra1.y), f2tf32(ra1.z), f2tf32(ra1.w));
        *(uint4*)&As[cur][lm][lk]      = ua0;
        *(uint4*)&As[cur][lm + 64][lk] = ua1;
        *(uint4*)&Bs[cur][lm][lk]      = rb0;
        *(uint4*)&Bs[cur][lm + 64][lk] = rb1;
        __syncthreads();

        if (it < 63) {
            int k0 = (it + 1) * 16;
            ra0 = *(const float4*)(Arow0 + k0);
            ra1 = *(const float4*)(Arow1 + k0);
            rb0 = *(const uint4*)(Brow0 + k0);
            rb1 = *(const uint4*)(Brow1 + k0);
        }

        #pragma unroll
        for (int ks = 0; ks < 16; ks += 8) {
            uint32_t afr[4][4];
            #pragma unroll
            for (int mt = 0; mt < 4; mt++) {
                uint32_t addr = as_u + cur * GBUF
                              + ((wm * 64 + mt * 16) * GSTR + ks) * 4 + a_inv;
                ldsm4(afr[mt], addr);
            }
            uint32_t bfr[4][2];
            #pragma unroll
            for (int p = 0; p < 2; p++) {
                uint32_t t[4];
                uint32_t addr = bs_u + cur * GBUF
                              + ((wn * 32 + 16 * p) * GSTR + ks) * 4 + b_inv;
                ldsm4(t, addr);
                bfr[2*p][0] = t[0]; bfr[2*p][1] = t[1];
                bfr[2*p+1][0] = t[2]; bfr[2*p+1][1] = t[3];
            }
            #pragma unroll
            for (int mt = 0; mt < 4; mt++)
                #pragma unroll
                for (int nt = 0; nt < 4; nt++)
                    mma_tf32(acc[mt][nt], afr[mt], bfr[nt]);
        }
        __syncthreads();
    }

    #pragma unroll
    for (int mt = 0; mt < 4; mt++) {
        int r0 = bm + wm * 64 + mt * 16 + grp;
        #pragma unroll
        for (int nt = 0; nt < 4; nt++) {
            int col = bn + wn * 32 + nt * 8 + q * 2;
            float b0 = bias[col], b1 = bias[col + 1];
            float2 v0 = make_float2(acc[mt][nt][0] + b0, acc[mt][nt][1] + b1);
            float2 v1 = make_float2(acc[mt][nt][2] + b0, acc[mt][nt][3] + b1);
            if (MODE == 1) {
                int which = col >> 10;
                int h = (col & 1023) >> 6;
                int d = col & 63;
                float* P = (which == 0) ? g_q : (which == 1) ? g_k : g_v;
                int b_0 = r0 >> 11, s0 = r0 & 2047;
                *(float2*)(P + (((size_t)(b_0 * NHEAD + h)) * S_LEN + s0) * DH + d) = v0;
                int r1 = r0 + 8;
                int b_1 = r1 >> 11, s1 = r1 & 2047;
                *(float2*)(P + (((size_t)(b_1 * NHEAD + h)) * S_LEN + s1) * DH + d) = v1;
            } else {
                *(float2*)(C + (size_t)r0 * DM + col) = v0;
                *(float2*)(C + (size_t)(r0 + 8) * DM + col) = v1;
            }
        }
    }
}

// ---------------------------------------------------------------------------
// Tensorized causal flash attention (tf32 mma.sync, online softmax).
// CTA: 128 q-rows (8 warps x 16 rows), key tiles of 64, Dh = 64.
// K and P/Q fragments via ldmatrix (strides 68 ≡ 4 mod 32: conflict-free);
// V fragments scalar LDS (stride 72: conflict-free).
// ---------------------------------------------------------------------------
#define PB_STRIDE 68
#define KS_STRIDE 68
#define VS_STRIDE 72
#define ATT_SMEM ((128*PB_STRIDE + 64*KS_STRIDE + 64*VS_STRIDE) * 4)  // 70656 B

__global__ __launch_bounds__(256, 2) void attn_mma_kernel()
{
    extern __shared__ uint32_t sm[];
    uint32_t (*Pbuf)[PB_STRIDE] = (uint32_t(*)[PB_STRIDE])sm;
    uint32_t (*Ks)[KS_STRIDE]   = (uint32_t(*)[KS_STRIDE])(sm + 128 * PB_STRIDE);
    uint32_t (*Vs)[VS_STRIDE]   = (uint32_t(*)[VS_STRIDE])(sm + 128 * PB_STRIDE + 64 * KS_STRIDE);

    const int qt = (int)gridDim.x - 1 - (int)blockIdx.x;   // heavy CTAs first
    const int bh = blockIdx.y;
    const int tid = threadIdx.x;
    const int lane = tid & 31;
    const int w = tid >> 5;
    const int grp = lane >> 2;
    const int q = lane & 3;

    const float scale = 0.125f;
    const float* qb = g_q + (size_t)bh * S_LEN * DH + (size_t)qt * 128 * DH;
    const float* kb = g_k + (size_t)bh * S_LEN * DH;
    const float* vb = g_v + (size_t)bh * S_LEN * DH;

    const uint32_t pb_u = smem_u32(&Pbuf[0][0]);
    const uint32_t ks_u = smem_u32(&Ks[0][0]);
    // A-pattern (P/Q) and B-pattern (K) ldmatrix lane offsets (bytes)
    const uint32_t p_inv = ((((lane >> 3) & 1) * 8 + (lane & 7)) * PB_STRIDE
                            + (((lane >> 4) & 1) << 2)) * 4;
    const uint32_t k_inv = ((((lane >> 4) & 1) * 8 + (lane & 7)) * KS_STRIDE
                            + (((lane >> 3) & 1) << 2)) * 4;

    // Stage Q (scaled, tf32)
    #pragma unroll
    for (int i = 0; i < 8; i++) {
        int idx = tid + 256 * i;
        int r = idx >> 4;
        int c4 = (idx & 15) << 2;
        float4 v = *(const float4*)(qb + (size_t)r * DH + c4);
        *(uint4*)&Pbuf[r][c4] = make_uint4(f2tf32(v.x * scale), f2tf32(v.y * scale),
                                           f2tf32(v.z * scale), f2tf32(v.w * scale));
    }
    __syncthreads();

    uint32_t aq[8][4];
    #pragma unroll
    for (int ks = 0; ks < 8; ks++)
        ldsm4(aq[ks], pb_u + ((w * 16) * PB_STRIDE + ks * 8) * 4 + p_inv);

    const int row0g = qt * 128 + w * 16 + grp;
    const int row1g = row0g + 8;

    float m0 = -INFINITY, m1 = -INFINITY;
    float l0 = 0.0f, l1 = 0.0f;
    float ao[8][4];
    #pragma unroll
    for (int nt = 0; nt < 8; nt++)
        #pragma unroll
        for (int r = 0; r < 4; r++) ao[nt][r] = 0.0f;

    const int nkt = 2 * qt + 2;
    #pragma unroll 1
    for (int kt = 0; kt < nkt; kt++) {
        __syncthreads();
        // Load K,V tile (64x64 each) -> tf32 SMEM (vector STS)
        #pragma unroll
        for (int i = 0; i < 4; i++) {
            int idx = tid + 256 * i;
            int r = idx >> 4;
            int c4 = (idx & 15) << 2;
            size_t g = (size_t)(kt * 64 + r) * DH + c4;
            float4 kv = *(const float4*)(kb + g);
            float4 vv = *(const float4*)(vb + g);
            *(uint4*)&Ks[r][c4] = make_uint4(f2tf32(kv.x), f2tf32(kv.y),
                                             f2tf32(kv.z), f2tf32(kv.w));
            *(uint4*)&Vs[r][c4] = make_uint4(f2tf32(vv.x), f2tf32(vv.y),
                                             f2tf32(vv.z), f2tf32(vv.w));
        }
        __syncthreads();

        // S = (Q*scale) K^T
        float sacc[8][4];
        #pragma unroll
        for (int nt = 0; nt < 8; nt++) {
            sacc[nt][0] = 0.0f; sacc[nt][1] = 0.0f;
            sacc[nt][2] = 0.0f; sacc[nt][3] = 0.0f;
        }
        #pragma unroll
        for (int ks = 0; ks < 8; ks++) {
            #pragma unroll
            for (int p = 0; p < 4; p++) {
                uint32_t t[4];
                ldsm4(t, ks_u + (16 * p * KS_STRIDE + ks * 8) * 4 + k_inv);
                mma_tf32(sacc[2*p],     aq[ks], &t[0]);
                mma_tf32(sacc[2*p + 1], aq[ks], &t[2]);
            }
        }

        // Causal mask (diagonal tiles only)
        if (kt >= 2 * qt) {
            #pragma unroll
            for (int nt = 0; nt < 8; nt++) {
                int c0g = kt * 64 + nt * 8 + 2 * q;
                if (c0g     > row0g) sacc[nt][0] = -INFINITY;
                if (c0g + 1 > row0g) sacc[nt][1] = -INFINITY;
                if (c0g     > row1g) sacc[nt][2] = -INFINITY;
                if (c0g + 1 > row1g) sacc[nt][3] = -INFINITY;
            }
        }

        // Online softmax
        float mt0 = -INFINITY, mt1 = -INFINITY;
        #pragma unroll
        for (int nt = 0; nt < 8; nt++) {
            mt0 = fmaxf(mt0, fmaxf(sacc[nt][0], sacc[nt][1]));
            mt1 = fmaxf(mt1, fmaxf(sacc[nt][2], sacc[nt][3]));
        }
        mt0 = fmaxf(mt0, __shfl_xor_sync(0xffffffffu, mt0, 1));
        mt0 = fmaxf(mt0, __shfl_xor_sync(0xffffffffu, mt0, 2));
        mt1 = fmaxf(mt1, __shfl_xor_sync(0xffffffffu, mt1, 1));
        mt1 = fmaxf(mt1, __shfl_xor_sync(0xffffffffu, mt1, 2));

        float mn0 = fmaxf(m0, mt0);
        float mn1 = fmaxf(m1, mt1);
        float al0 = __expf(m0 - mn0);
        float al1 = __expf(m1 - mn1);

        float rs0 = 0.0f, rs1 = 0.0f;
        int pr0 = w * 16 + grp;
        #pragma unroll
        for (int nt = 0; nt < 8; nt++) {
            float p0 = __expf(sacc[nt][0] - mn0);
            float p1 = __expf(sacc[nt][1] - mn0);
            float p2 = __expf(sacc[nt][2] - mn1);
            float p3 = __expf(sacc[nt][3] - mn1);
            rs0 += p0 + p1;
            rs1 += p2 + p3;
            *(uint2*)&Pbuf[pr0][nt * 8 + 2 * q]     = make_uint2(f2tf32(p0), f2tf32(p1));
            *(uint2*)&Pbuf[pr0 + 8][nt * 8 + 2 * q] = make_uint2(f2tf32(p2), f2tf32(p3));
        }
        rs0 += __shfl_xor_sync(0xffffffffu, rs0, 1);
        rs0 += __shfl_xor_sync(0xffffffffu, rs0, 2);
        rs1 += __shfl_xor_sync(0xffffffffu, rs1, 1);
        rs1 += __shfl_xor_sync(0xffffffffu, rs1, 2);

        l0 = l0 * al0 + rs0;
        l1 = l1 * al1 + rs1;
        m0 = mn0;
        m1 = mn1;

        #pragma unroll
        for (int nt = 0; nt < 8; nt++) {
            ao[nt][0] *= al0; ao[nt][1] *= al0;
            ao[nt][2] *= al1; ao[nt][3] *= al1;
        }

        __syncwarp();   // P staging is warp-local

        // O += P @ V
        #pragma unroll
        for (int ks = 0; ks < 8; ks++) {
            uint32_t ap[4];
            ldsm4(ap, pb_u + ((w * 16) * PB_STRIDE + ks * 8) * 4 + p_inv);
            #pragma unroll
            for (int nt = 0; nt < 8; nt++) {
                uint32_t bfr[2];
                bfr[0] = Vs[ks * 8 + q][nt * 8 + grp];
                bfr[1] = Vs[ks * 8 + q + 4][nt * 8 + grp];
                mma_tf32(ao[nt], ap, bfr);
            }
        }
        __syncwarp();
    }

    // Epilogue -> g_o[b*2048+s][h*64+d]
    float inv0 = 1.0f / l0;
    float inv1 = 1.0f / l1;
    int b = bh >> 4;
    int h = bh & 15;
    float* o0 = g_o + ((size_t)(b * S_LEN + row0g)) * DM + h * DH;
    float* o1 = g_o + ((size_t)(b * S_LEN + row1g)) * DM + h * DH;
    #pragma unroll
    for (int nt = 0; nt < 8; nt++) {
        int col = nt * 8 + 2 * q;
        *(float2*)(o0 + col) = make_float2(ao[nt][0] * inv0, ao[nt][1] * inv0);
        *(float2*)(o1 + col) = make_float2(ao[nt][2] * inv1, ao[nt][3] * inv1);
    }
}

// ---------------------------------------------------------------------------
extern "C" void kernel_launch(void* const* d_in, const int* in_sizes, int n_in,
                              void* d_out, int out_size)
{
    const float* x     = (const float*)d_in[0];
    const float* W_qkv = (const float*)d_in[1];
    const float* b_qkv = (const float*)d_in[2];
    const float* W_out = (const float*)d_in[3];
    const float* b_out = (const float*)d_in[4];
    float* out = (float*)d_out;

    cudaFuncSetAttribute(attn_mma_kernel,
                         cudaFuncAttributeMaxDynamicSharedMemorySize, ATT_SMEM);

    uint32_t* wt;  cudaGetSymbolAddress((void**)&wt, g_wt);
    uint32_t* wo;  cudaGetSymbolAddress((void**)&wo, g_wo);

    // 0) Transpose weights to K-major (+ tf32 pre-conversion)
    {
        dim3 blk(32, 8);
        transpose_tf32_kernel<<<dim3(3 * DM / 32, DM / 32), blk>>>(W_qkv, wt, DM, 3 * DM);
        transpose_tf32_kernel<<<dim3(DM / 32, DM / 32), blk>>>(W_out, wo, DM, DM);
    }

    // 1) QKV projection -> scatter to g_q/g_k/g_v
    {
        dim3 grid(3 * DM / 128, MROWS / 128);   // (24, 64)
        mma_gemm<1><<<grid, 256>>>(x, b_qkv, nullptr);
    }

    // 2) Tensorized causal flash attention -> g_o
    {
        dim3 grid(S_LEN / 128, BHTOT);          // (16, 64)
        attn_mma_kernel<<<grid, 256, ATT_SMEM>>>();
    }

    // 3) Output projection -> d_out
    {
        dim3 grid(DM / 128, MROWS / 128);       // (8, 64)
        mma_gemm<0><<<grid, 256>>>(nullptr, b_out, out);
    }
}

// round 6
// speedup vs baseline: 4.7179x; 1.2414x over previous
#include <cuda_runtime.h>
#include <cuda_fp16.h>
#include <math.h>
#include <stdint.h>

// Problem constants
#define BATCH   4
#define S_LEN   2048
#define NHEAD   16
#define DH      64
#define DM      1024
#define BHTOT   (BATCH*NHEAD)   // 64
#define MROWS   (BATCH*S_LEN)   // 8192

// Scratch (device globals: allocation-free, graph-capturable)
__device__ __half g_q[(size_t)BHTOT * S_LEN * DH];
__device__ __half g_k[(size_t)BHTOT * S_LEN * DH];
__device__ __half g_v[(size_t)BHTOT * S_LEN * DH];
__device__ __half g_o[(size_t)MROWS * DM];
__device__ __half g_wt[(size_t)3 * DM * DM];   // W_qkv^T fp16 : [3072][1024]
__device__ __half g_wo[(size_t)DM * DM];       // W_out^T fp16 : [1024][1024]

// ---------------------------------------------------------------------------
__device__ __forceinline__ void mma_f16(float* c, const uint32_t* a, const uint32_t* b) {
    asm volatile(
        "mma.sync.aligned.m16n8k16.row.col.f32.f16.f16.f32 "
        "{%0,%1,%2,%3}, {%4,%5,%6,%7}, {%8,%9}, {%0,%1,%2,%3};"
        : "+f"(c[0]), "+f"(c[1]), "+f"(c[2]), "+f"(c[3])
        : "r"(a[0]), "r"(a[1]), "r"(a[2]), "r"(a[3]), "r"(b[0]), "r"(b[1]));
}
__device__ __forceinline__ void ldsm4(uint32_t* r, uint32_t addr) {
    asm volatile("ldmatrix.sync.aligned.m8n8.x4.shared.b16 {%0,%1,%2,%3}, [%4];"
                 : "=r"(r[0]), "=r"(r[1]), "=r"(r[2]), "=r"(r[3]) : "r"(addr));
}
__device__ __forceinline__ void ldsm4t(uint32_t* r, uint32_t addr) {
    asm volatile("ldmatrix.sync.aligned.m8n8.x4.trans.shared.b16 {%0,%1,%2,%3}, [%4];"
                 : "=r"(r[0]), "=r"(r[1]), "=r"(r[2]), "=r"(r[3]) : "r"(addr));
}
__device__ __forceinline__ uint32_t smem_u32(const void* p) {
    uint32_t a;
    asm("{ .reg .u64 t; cvta.to.shared.u64 t, %1; cvt.u32.u64 %0, t; }"
        : "=r"(a) : "l"(p));
    return a;
}
__device__ __forceinline__ uint32_t pack_h2(float lo, float hi) {
    __half2 h = __floats2half2_rn(lo, hi);
    return *(uint32_t*)&h;
}

// ---------------------------------------------------------------------------
// Transpose + fp16-convert: out[c][r] = half(in[r][c]).  in: [R][C].
// ---------------------------------------------------------------------------
__global__ void transpose_f16_kernel(const float* __restrict__ in,
                                     __half* __restrict__ out, int R, int C)
{
    __shared__ float t[32][33];
    int bx = blockIdx.x * 32, by = blockIdx.y * 32;
    int x = threadIdx.x, y0 = threadIdx.y;
    #pragma unroll
    for (int i = 0; i < 32; i += 8)
        t[y0 + i][x] = in[(size_t)(by + y0 + i) * C + bx + x];
    __syncthreads();
    #pragma unroll
    for (int i = 0; i < 32; i += 8)
        out[(size_t)(bx + y0 + i) * R + by + x] = __float2half(t[x][y0 + i]);
}

// ---------------------------------------------------------------------------
// fp16 mma.sync GEMM.  C = A @ B^T + bias (K-major operands), fp32 accum.
// CTA tile 128x128, BK=32 halves, 256 threads = 8 warps (2Mx4N), warp 64x32.
// SMEM row stride 40 halves (80B, 20 words ≡ 20 mod 32: conflict-free ldsm).
// MODE 1: A = x (fp32), B = g_wt, scatter fp16 epilogue to g_q/g_k/g_v
// MODE 0: A = g_o (fp16), B = g_wo, C = d_out (fp32)
// ---------------------------------------------------------------------------
#define GSTR 40                         // halves per smem row
#define GBUF (128*GSTR*2)               // bytes per tile buffer

template <int MODE>
__global__ __launch_bounds__(256, 2) void mma_gemm(
    const float* __restrict__ Ax, const float* __restrict__ bias,
    float* __restrict__ C)
{
    __shared__ __half As[2][128][GSTR];
    __shared__ __half Bs[2][128][GSTR];

    const __half* Bg = (MODE == 1) ? g_wt : g_wo;

    const int tid = threadIdx.x;
    const int lane = tid & 31;
    const int wid = tid >> 5;
    const int wm = wid & 1;
    const int wn = wid >> 1;
    const int bm = blockIdx.y * 128;
    const int bn = blockIdx.x * 128;

    // fill mapping: row = tid&127, 16-half chunk index c16 = tid>>7
    const int fr = tid & 127;
    const int fc = tid >> 7;            // 0 or 1

    const uint32_t as_u = smem_u32(&As[0][0][0]);
    const uint32_t bs_u = smem_u32(&Bs[0][0][0]);
    const uint32_t lm_inv = ((lane & 15) * GSTR + ((lane >> 4) << 3)) * 2;  // bytes

    float acc[4][4][4];
    #pragma unroll
    for (int mt = 0; mt < 4; mt++)
        #pragma unroll
        for (int nt = 0; nt < 4; nt++)
            #pragma unroll
            for (int r = 0; r < 4; r++) acc[mt][nt][r] = 0.0f;

    const int grp = lane >> 2;
    const int q = lane & 3;

    // prefetch regs
    float4 pa[4];
    uint4 pb0, pb1;
    {
        const __half* bp = Bg + (size_t)(bn + fr) * 1024 + fc * 16;
        pb0 = *(const uint4*)(bp);
        pb1 = *(const uint4*)(bp + 8);
        if (MODE == 1) {
            const float* ap = Ax + (size_t)(bm + fr) * 1024 + fc * 16;
            pa[0] = *(const float4*)(ap);
            pa[1] = *(const float4*)(ap + 4);
            pa[2] = *(const float4*)(ap + 8);
            pa[3] = *(const float4*)(ap + 12);
        } else {
            const __half* ap = g_o + (size_t)(bm + fr) * 1024 + fc * 16;
            pa[0] = *(const float4*)&(*(const uint4*)(ap));        // raw halves
            pa[1] = *(const float4*)&(*(const uint4*)(ap + 8));
        }
    }

    #pragma unroll 1
    for (int it = 0; it < 32; it++) {
        int cur = it & 1;
        // store prefetched chunk
        if (MODE == 1) {
            uint4 u;
            u.x = pack_h2(pa[0].x, pa[0].y); u.y = pack_h2(pa[0].z, pa[0].w);
            u.z = pack_h2(pa[1].x, pa[1].y); u.w = pack_h2(pa[1].z, pa[1].w);
            *(uint4*)&As[cur][fr][fc * 16] = u;
            u.x = pack_h2(pa[2].x, pa[2].y); u.y = pack_h2(pa[2].z, pa[2].w);
            u.z = pack_h2(pa[3].x, pa[3].y); u.w = pack_h2(pa[3].z, pa[3].w);
            *(uint4*)&As[cur][fr][fc * 16 + 8] = u;
        } else {
            *(uint4*)&As[cur][fr][fc * 16]     = *(const uint4*)&pa[0];
            *(uint4*)&As[cur][fr][fc * 16 + 8] = *(const uint4*)&pa[1];
        }
        *(uint4*)&Bs[cur][fr][fc * 16]     = pb0;
        *(uint4*)&Bs[cur][fr][fc * 16 + 8] = pb1;
        __syncthreads();

        if (it < 31) {
            int k0 = (it + 1) * 32;
            const __half* bp = Bg + (size_t)(bn + fr) * 1024 + k0 + fc * 16;
            pb0 = *(const uint4*)(bp);
            pb1 = *(const uint4*)(bp + 8);
            if (MODE == 1) {
                const float* ap = Ax + (size_t)(bm + fr) * 1024 + k0 + fc * 16;
                pa[0] = *(const float4*)(ap);
                pa[1] = *(const float4*)(ap + 4);
                pa[2] = *(const float4*)(ap + 8);
                pa[3] = *(const float4*)(ap + 12);
            } else {
                const __half* ap = g_o + (size_t)(bm + fr) * 1024 + k0 + fc * 16;
                pa[0] = *(const float4*)&(*(const uint4*)(ap));
                pa[1] = *(const float4*)&(*(const uint4*)(ap + 8));
            }
        }

        #pragma unroll
        for (int ks = 0; ks < 2; ks++) {
            uint32_t afr[4][4];
            #pragma unroll
            for (int mt = 0; mt < 4; mt++)
                ldsm4(afr[mt], as_u + cur * GBUF
                      + ((wm * 64 + mt * 16) * GSTR) * 2 + ks * 32 + lm_inv);
            uint32_t bfr[4][2];
            #pragma unroll
            for (int p = 0; p < 2; p++) {
                uint32_t t[4];
                ldsm4(t, bs_u + cur * GBUF
                      + ((wn * 32 + p * 16) * GSTR) * 2 + ks * 32 + lm_inv);
                bfr[2*p][0] = t[0]; bfr[2*p][1] = t[2];
                bfr[2*p+1][0] = t[1]; bfr[2*p+1][1] = t[3];
            }
            #pragma unroll
            for (int mt = 0; mt < 4; mt++)
                #pragma unroll
                for (int nt = 0; nt < 4; nt++)
                    mma_f16(acc[mt][nt], afr[mt], bfr[nt]);
        }
        __syncthreads();
    }

    // Epilogue
    #pragma unroll
    for (int mt = 0; mt < 4; mt++) {
        int r0 = bm + wm * 64 + mt * 16 + grp;
        #pragma unroll
        for (int nt = 0; nt < 4; nt++) {
            int col = bn + wn * 32 + nt * 8 + q * 2;
            float b0 = bias[col], b1 = bias[col + 1];
            float v00 = acc[mt][nt][0] + b0, v01 = acc[mt][nt][1] + b1;
            float v10 = acc[mt][nt][2] + b0, v11 = acc[mt][nt][3] + b1;
            if (MODE == 1) {
                int which = col >> 10;
                int h = (col & 1023) >> 6;
                int d = col & 63;
                __half* P = (which == 0) ? g_q : (which == 1) ? g_k : g_v;
                int b_0 = r0 >> 11, s0 = r0 & 2047;
                *(uint32_t*)(P + (((size_t)(b_0 * NHEAD + h)) * S_LEN + s0) * DH + d)
                    = pack_h2(v00, v01);
                int r1 = r0 + 8;
                int b_1 = r1 >> 11, s1 = r1 & 2047;
                *(uint32_t*)(P + (((size_t)(b_1 * NHEAD + h)) * S_LEN + s1) * DH + d)
                    = pack_h2(v10, v11);
            } else {
                *(float2*)(C + (size_t)r0 * DM + col) = make_float2(v00, v01);
                *(float2*)(C + (size_t)(r0 + 8) * DM + col) = make_float2(v10, v11);
            }
        }
    }
}

// ---------------------------------------------------------------------------
// fp16 tensorized causal flash attention.  CTA: 128 q-rows (8 warps x 16),
// key tiles of 64, Dh=64.  Q/K/V smem stride 72 halves (36 words ≡ 4 mod 32).
// P stays in registers (S-frag -> A-frag identity); V via ldmatrix.trans.
// ---------------------------------------------------------------------------
#define ASTR 72                          // halves per smem row
#define QS_BYTES (128 * ASTR * 2)
#define KS_BYTES (64 * ASTR * 2)
#define ATT_SMEM (QS_BYTES + 2 * KS_BYTES)   // 36864 B

__global__ __launch_bounds__(256, 2) void attn_mma_kernel()
{
    extern __shared__ __half smh[];
    __half* Qs = smh;                        // [128][ASTR]
    __half* Ksm = smh + 128 * ASTR;          // [64][ASTR]
    __half* Vsm = Ksm + 64 * ASTR;           // [64][ASTR]

    const int qt = (int)gridDim.x - 1 - (int)blockIdx.x;   // heavy CTAs first
    const int bh = blockIdx.y;
    const int tid = threadIdx.x;
    const int lane = tid & 31;
    const int w = tid >> 5;
    const int grp = lane >> 2;
    const int q = lane & 3;

    const __half* qb = g_q + (size_t)bh * S_LEN * DH + (size_t)qt * 128 * DH;
    const __half* kb = g_k + (size_t)bh * S_LEN * DH;
    const __half* vb = g_v + (size_t)bh * S_LEN * DH;

    const uint32_t qs_u = smem_u32(Qs);
    const uint32_t ks_u = smem_u32(Ksm);
    const uint32_t vs_u = smem_u32(Vsm);
    const uint32_t lm_inv = ((lane & 15) * ASTR + ((lane >> 4) << 3)) * 2;  // bytes

    // Stage Q (fp16, already scaled? no: apply scale to S after MMA is wrong
    // for max-subtraction? fine: scale applied to scores pre-mask via multiply)
    #pragma unroll
    for (int i = 0; i < 4; i++) {
        int c = tid + 256 * i;               // 8-half chunk id over 128x64
        int r = c >> 3;
        int c8 = (c & 7) * 8;
        *(uint4*)(Qs + r * ASTR + c8) = *(const uint4*)(qb + r * DH + c8);
    }
    __syncthreads();

    uint32_t aq[4][4];
    #pragma unroll
    for (int ks = 0; ks < 4; ks++)
        ldsm4(aq[ks], qs_u + (w * 16 * ASTR) * 2 + ks * 32 + lm_inv);

    const int row0g = qt * 128 + w * 16 + grp;
    const int row1g = row0g + 8;
    const float scale = 0.125f;

    float m0 = -INFINITY, m1 = -INFINITY;
    float l0 = 0.0f, l1 = 0.0f;
    float ao[8][4];
    #pragma unroll
    for (int nt = 0; nt < 8; nt++)
        #pragma unroll
        for (int r = 0; r < 4; r++) ao[nt][r] = 0.0f;

    const int nkt = 2 * qt + 2;
    #pragma unroll 1
    for (int kt = 0; kt < nkt; kt++) {
        __syncthreads();
        // Fill K,V tiles (64x64 halves each)
        #pragma unroll
        for (int i = 0; i < 4; i++) {
            int c = tid + 256 * i;           // 0..1023 chunks; first 512 K, rest V
            int cc = c & 511;
            int r = cc >> 3;
            int c8 = (cc & 7) * 8;
            const __half* src = (c < 512) ? kb : vb;
            __half* dst = (c < 512) ? Ksm : Vsm;
            *(uint4*)(dst + r * ASTR + c8) =
                *(const uint4*)(src + (size_t)(kt * 64 + r) * DH + c8);
        }
        __syncthreads();

        // S = Q K^T (fp32 accum), then *scale
        float sacc[8][4];
        #pragma unroll
        for (int nt = 0; nt < 8; nt++) {
            sacc[nt][0] = 0.0f; sacc[nt][1] = 0.0f;
            sacc[nt][2] = 0.0f; sacc[nt][3] = 0.0f;
        }
        #pragma unroll
        for (int ks = 0; ks < 4; ks++) {
            #pragma unroll
            for (int p = 0; p < 4; p++) {
                uint32_t t[4];
                ldsm4(t, ks_u + (p * 16 * ASTR) * 2 + ks * 32 + lm_inv);
                uint32_t b0[2] = {t[0], t[2]};
                uint32_t b1[2] = {t[1], t[3]};
                mma_f16(sacc[2*p],     aq[ks], b0);
                mma_f16(sacc[2*p + 1], aq[ks], b1);
            }
        }
        #pragma unroll
        for (int nt = 0; nt < 8; nt++) {
            sacc[nt][0] *= scale; sacc[nt][1] *= scale;
            sacc[nt][2] *= scale; sacc[nt][3] *= scale;
        }

        // Causal mask (diagonal tiles only)
        if (kt >= 2 * qt) {
            #pragma unroll
            for (int nt = 0; nt < 8; nt++) {
                int c0g = kt * 64 + nt * 8 + 2 * q;
                if (c0g     > row0g) sacc[nt][0] = -INFINITY;
                if (c0g + 1 > row0g) sacc[nt][1] = -INFINITY;
                if (c0g     > row1g) sacc[nt][2] = -INFINITY;
                if (c0g + 1 > row1g) sacc[nt][3] = -INFINITY;
            }
        }

        // Online softmax
        float mt0 = -INFINITY, mt1 = -INFINITY;
        #pragma unroll
        for (int nt = 0; nt < 8; nt++) {
            mt0 = fmaxf(mt0, fmaxf(sacc[nt][0], sacc[nt][1]));
            mt1 = fmaxf(mt1, fmaxf(sacc[nt][2], sacc[nt][3]));
        }
        mt0 = fmaxf(mt0, __shfl_xor_sync(0xffffffffu, mt0, 1));
        mt0 = fmaxf(mt0, __shfl_xor_sync(0xffffffffu, mt0, 2));
        mt1 = fmaxf(mt1, __shfl_xor_sync(0xffffffffu, mt1, 1));
        mt1 = fmaxf(mt1, __shfl_xor_sync(0xffffffffu, mt1, 2));

        float mn0 = fmaxf(m0, mt0);
        float mn1 = fmaxf(m1, mt1);
        float al0 = __expf(m0 - mn0);
        float al1 = __expf(m1 - mn1);

        float rs0 = 0.0f, rs1 = 0.0f;
        #pragma unroll
        for (int nt = 0; nt < 8; nt++) {
            sacc[nt][0] = __expf(sacc[nt][0] - mn0);
            sacc[nt][1] = __expf(sacc[nt][1] - mn0);
            sacc[nt][2] = __expf(sacc[nt][2] - mn1);
            sacc[nt][3] = __expf(sacc[nt][3] - mn1);
            rs0 += sacc[nt][0] + sacc[nt][1];
            rs1 += sacc[nt][2] + sacc[nt][3];
        }
        rs0 += __shfl_xor_sync(0xffffffffu, rs0, 1);
        rs0 += __shfl_xor_sync(0xffffffffu, rs0, 2);
        rs1 += __shfl_xor_sync(0xffffffffu, rs1, 1);
        rs1 += __shfl_xor_sync(0xffffffffu, rs1, 2);

        l0 = l0 * al0 + rs0;
        l1 = l1 * al1 + rs1;
        m0 = mn0;
        m1 = mn1;

        #pragma unroll
        for (int nt = 0; nt < 8; nt++) {
            ao[nt][0] *= al0; ao[nt][1] *= al0;
            ao[nt][2] *= al1; ao[nt][3] *= al1;
        }

        // P fragments directly from S accumulators (no SMEM round-trip)
        uint32_t ap[4][4];
        #pragma unroll
        for (int ks = 0; ks < 4; ks++) {
            ap[ks][0] = pack_h2(sacc[2*ks][0],     sacc[2*ks][1]);
            ap[ks][1] = pack_h2(sacc[2*ks][2],     sacc[2*ks][3]);
            ap[ks][2] = pack_h2(sacc[2*ks + 1][0], sacc[2*ks + 1][1]);
            ap[ks][3] = pack_h2(sacc[2*ks + 1][2], sacc[2*ks + 1][3]);
        }

        // O += P @ V  (V B-fragments via ldmatrix.trans from [key][dh])
        #pragma unroll
        for (int ks = 0; ks < 4; ks++) {
            #pragma unroll
            for (int p = 0; p < 4; p++) {
                uint32_t t[4];
                ldsm4t(t, vs_u + (ks * 16 * ASTR) * 2 + p * 32 + lm_inv);
                mma_f16(ao[2*p],     ap[ks], &t[0]);
                mma_f16(ao[2*p + 1], ap[ks], &t[2]);
            }
        }
    }

    // Epilogue -> g_o (fp16) [b*2048+s][h*64+d]
    float inv0 = 1.0f / l0;
    float inv1 = 1.0f / l1;
    int b = bh >> 4;
    int h = bh & 15;
    __half* o0 = g_o + ((size_t)(b * S_LEN + row0g)) * DM + h * DH;
    __half* o1 = g_o + ((size_t)(b * S_LEN + row1g)) * DM + h * DH;
    #pragma unroll
    for (int nt = 0; nt < 8; nt++) {
        int col = nt * 8 + 2 * q;
        *(uint32_t*)(o0 + col) = pack_h2(ao[nt][0] * inv0, ao[nt][1] * inv0);
        *(uint32_t*)(o1 + col) = pack_h2(ao[nt][2] * inv1, ao[nt][3] * inv1);
    }
}

// ---------------------------------------------------------------------------
extern "C" void kernel_launch(void* const* d_in, const int* in_sizes, int n_in,
                              void* d_out, int out_size)
{
    const float* x     = (const float*)d_in[0];
    const float* W_qkv = (const float*)d_in[1];
    const float* b_qkv = (const float*)d_in[2];
    const float* W_out = (const float*)d_in[3];
    const float* b_out = (const float*)d_in[4];
    float* out = (float*)d_out;

    cudaFuncSetAttribute(attn_mma_kernel,
                         cudaFuncAttributeMaxDynamicSharedMemorySize, ATT_SMEM);

    __half* wt;  cudaGetSymbolAddress((void**)&wt, g_wt);
    __half* wo;  cudaGetSymbolAddress((void**)&wo, g_wo);

    // 0) Transpose weights to K-major fp16
    {
        dim3 blk(32, 8);
        transpose_f16_kernel<<<dim3(3 * DM / 32, DM / 32), blk>>>(W_qkv, wt, DM, 3 * DM);
        transpose_f16_kernel<<<dim3(DM / 32, DM / 32), blk>>>(W_out, wo, DM, DM);
    }

    // 1) QKV projection -> fp16 scatter to g_q/g_k/g_v
    {
        dim3 grid(3 * DM / 128, MROWS / 128);   // (24, 64)
        mma_gemm<1><<<grid, 256>>>(x, b_qkv, nullptr);
    }

    // 2) fp16 tensorized causal flash attention -> g_o (fp16)
    {
        dim3 grid(S_LEN / 128, BHTOT);          // (16, 64)
        attn_mma_kernel<<<grid, 256, ATT_SMEM>>>();
    }

    // 3) Output projection -> d_out (fp32)
    {
        dim3 grid(DM / 128, MROWS / 128);       // (8, 64)
        mma_gemm<0><<<grid, 256>>>(nullptr, b_out, out);
    }
}

// round 7
// speedup vs baseline: 7.0355x; 1.4912x over previous
#include <cuda_runtime.h>
#include <cuda_fp16.h>
#include <math.h>
#include <stdint.h>

// Problem constants
#define BATCH   4
#define S_LEN   2048
#define NHEAD   16
#define DH      64
#define DM      1024
#define BHTOT   (BATCH*NHEAD)   // 64
#define MROWS   (BATCH*S_LEN)   // 8192

// Scratch (device globals: allocation-free, graph-capturable)
__device__ __half g_q[(size_t)BHTOT * S_LEN * DH];
__device__ __half g_k[(size_t)BHTOT * S_LEN * DH];
__device__ __half g_v[(size_t)BHTOT * S_LEN * DH];
__device__ __half g_o[(size_t)MROWS * DM];
__device__ __half g_x16[(size_t)MROWS * DM];     // x converted to fp16
__device__ __half g_wt[(size_t)3 * DM * DM];     // W_qkv^T fp16 : [3072][1024]
__device__ __half g_wo[(size_t)DM * DM];         // W_out^T fp16 : [1024][1024]

// ---------------------------------------------------------------------------
__device__ __forceinline__ void mma_f16(float* c, const uint32_t* a, const uint32_t* b) {
    asm volatile(
        "mma.sync.aligned.m16n8k16.row.col.f32.f16.f16.f32 "
        "{%0,%1,%2,%3}, {%4,%5,%6,%7}, {%8,%9}, {%0,%1,%2,%3};"
        : "+f"(c[0]), "+f"(c[1]), "+f"(c[2]), "+f"(c[3])
        : "r"(a[0]), "r"(a[1]), "r"(a[2]), "r"(a[3]), "r"(b[0]), "r"(b[1]));
}
__device__ __forceinline__ void ldsm4(uint32_t* r, uint32_t addr) {
    asm volatile("ldmatrix.sync.aligned.m8n8.x4.shared.b16 {%0,%1,%2,%3}, [%4];"
                 : "=r"(r[0]), "=r"(r[1]), "=r"(r[2]), "=r"(r[3]) : "r"(addr));
}
__device__ __forceinline__ void ldsm4t(uint32_t* r, uint32_t addr) {
    asm volatile("ldmatrix.sync.aligned.m8n8.x4.trans.shared.b16 {%0,%1,%2,%3}, [%4];"
                 : "=r"(r[0]), "=r"(r[1]), "=r"(r[2]), "=r"(r[3]) : "r"(addr));
}
__device__ __forceinline__ uint32_t smem_u32(const void* p) {
    uint32_t a;
    asm("{ .reg .u64 t; cvta.to.shared.u64 t, %1; cvt.u32.u64 %0, t; }"
        : "=r"(a) : "l"(p));
    return a;
}
__device__ __forceinline__ uint32_t pack_h2(float lo, float hi) {
    __half2 h = __floats2half2_rn(lo, hi);
    return *(uint32_t*)&h;
}
__device__ __forceinline__ void cp_async16(uint32_t s, const void* g) {
    asm volatile("cp.async.cg.shared.global [%0], [%1], 16;" :: "r"(s), "l"(g));
}
__device__ __forceinline__ void cp_commit() {
    asm volatile("cp.async.commit_group;");
}
template <int N>
__device__ __forceinline__ void cp_wait() {
    asm volatile("cp.async.wait_group %0;" :: "n"(N));
}

// ---------------------------------------------------------------------------
// x (fp32) -> g_x16 (fp16).  8 floats per thread.
// ---------------------------------------------------------------------------
__global__ void f32_to_f16_kernel(const float* __restrict__ in, __half* __restrict__ out)
{
    size_t i = ((size_t)blockIdx.x * blockDim.x + threadIdx.x) * 8;
    float4 a = *(const float4*)(in + i);
    float4 b = *(const float4*)(in + i + 4);
    uint4 u;
    u.x = pack_h2(a.x, a.y); u.y = pack_h2(a.z, a.w);
    u.z = pack_h2(b.x, b.y); u.w = pack_h2(b.z, b.w);
    *(uint4*)(out + i) = u;
}

// ---------------------------------------------------------------------------
// Transpose + fp16-convert: out[c][r] = half(in[r][c]).  in: [R][C].
// ---------------------------------------------------------------------------
__global__ void transpose_f16_kernel(const float* __restrict__ in,
                                     __half* __restrict__ out, int R, int C)
{
    __shared__ float t[32][33];
    int bx = blockIdx.x * 32, by = blockIdx.y * 32;
    int x = threadIdx.x, y0 = threadIdx.y;
    #pragma unroll
    for (int i = 0; i < 32; i += 8)
        t[y0 + i][x] = in[(size_t)(by + y0 + i) * C + bx + x];
    __syncthreads();
    #pragma unroll
    for (int i = 0; i < 32; i += 8)
        out[(size_t)(bx + y0 + i) * R + by + x] = __float2half(t[x][y0 + i]);
}

// ---------------------------------------------------------------------------
// fp16 mma.sync GEMM with 4-stage cp.async pipeline.
// C = A @ B^T + bias (K-major fp16 operands), fp32 accum.
// CTA tile 128x128, BK=32 halves, 256 threads = 8 warps (2Mx4N), warp 64x32.
// SMEM row stride 40 halves; dynamic smem = 2*4*10240 = 81920 B.
// MODE 1: A = g_x16, B = g_wt (N=3072), scatter fp16 epilogue to g_q/g_k/g_v
// MODE 0: A = g_o,  B = g_wo (N=1024), C = d_out (fp32)
// ---------------------------------------------------------------------------
#define GSTR 40                          // halves per smem row
#define STAGE_BYTES (128 * GSTR * 2)     // 10240
#define STAGES 4
#define GEMM_SMEM (2 * STAGES * STAGE_BYTES)   // 81920

template <int MODE>
__global__ __launch_bounds__(256, 2) void mma_gemm(
    const float* __restrict__ bias, float* __restrict__ C)
{
    extern __shared__ __half smg[];
    const uint32_t as_u = smem_u32(smg);                      // A stages
    const uint32_t bs_u = as_u + STAGES * STAGE_BYTES;        // B stages

    const __half* Ag = (MODE == 1) ? g_x16 : g_o;
    const __half* Bg = (MODE == 1) ? g_wt : g_wo;

    const int tid = threadIdx.x;
    const int lane = tid & 31;
    const int wid = tid >> 5;
    const int wm = wid & 1;
    const int wn = wid >> 1;
    const int bm = blockIdx.y * 128;
    const int bn = blockIdx.x * 128;

    const uint32_t lm_inv = ((lane & 15) * GSTR + ((lane >> 4) << 3)) * 2;  // bytes
    const int grp = lane >> 2;
    const int q = lane & 3;

    float acc[4][4][4];
    #pragma unroll
    for (int mt = 0; mt < 4; mt++)
        #pragma unroll
        for (int nt = 0; nt < 4; nt++)
            #pragma unroll
            for (int r = 0; r < 4; r++) acc[mt][nt][r] = 0.0f;

    // cp.async fill of one stage: 1024 16B chunks (512 A + 512 B), 4/thread
    auto issue_stage = [&](int st, int k0) {
        #pragma unroll
        for (int i = 0; i < 4; i++) {
            int c = tid + 256 * i;
            int cc = c & 511;
            int r = cc >> 2;
            int off8 = (cc & 3) * 8;
            const __half* src = ((c < 512)
                ? (Ag + (size_t)(bm + r) * 1024)
                : (Bg + (size_t)(bn + r) * 1024)) + k0 + off8;
            uint32_t dst = ((c < 512) ? as_u : bs_u)
                         + st * STAGE_BYTES + (r * GSTR + off8) * 2;
            cp_async16(dst, src);
        }
        cp_commit();
    };

    issue_stage(0, 0);
    issue_stage(1, 32);
    issue_stage(2, 64);

    #pragma unroll 1
    for (int it = 0; it < 32; it++) {
        if (it < 30) cp_wait<2>(); else cp_wait<0>();
        __syncthreads();
        int st = it & 3;

        #pragma unroll
        for (int ks = 0; ks < 2; ks++) {
            uint32_t afr[4][4];
            #pragma unroll
            for (int mt = 0; mt < 4; mt++)
                ldsm4(afr[mt], as_u + st * STAGE_BYTES
                      + ((wm * 64 + mt * 16) * GSTR) * 2 + ks * 32 + lm_inv);
            uint32_t bfr[4][2];
            #pragma unroll
            for (int p = 0; p < 2; p++) {
                uint32_t t[4];
                ldsm4(t, bs_u + st * STAGE_BYTES
                      + ((wn * 32 + p * 16) * GSTR) * 2 + ks * 32 + lm_inv);
                bfr[2*p][0] = t[0]; bfr[2*p][1] = t[2];
                bfr[2*p+1][0] = t[1]; bfr[2*p+1][1] = t[3];
            }
            #pragma unroll
            for (int mt = 0; mt < 4; mt++)
                #pragma unroll
                for (int nt = 0; nt < 4; nt++)
                    mma_f16(acc[mt][nt], afr[mt], bfr[nt]);
        }

        if (it + 3 < 32) {
            __syncthreads();    // all warps done reading stage (it+3)&3 (filled it-1)
            issue_stage((it + 3) & 3, (it + 3) * 32);
        }
    }

    // Epilogue
    #pragma unroll
    for (int mt = 0; mt < 4; mt++) {
        int r0 = bm + wm * 64 + mt * 16 + grp;
        #pragma unroll
        for (int nt = 0; nt < 4; nt++) {
            int col = bn + wn * 32 + nt * 8 + q * 2;
            float b0 = bias[col], b1 = bias[col + 1];
            float v00 = acc[mt][nt][0] + b0, v01 = acc[mt][nt][1] + b1;
            float v10 = acc[mt][nt][2] + b0, v11 = acc[mt][nt][3] + b1;
            if (MODE == 1) {
                int which = col >> 10;
                int h = (col & 1023) >> 6;
                int d = col & 63;
                __half* P = (which == 0) ? g_q : (which == 1) ? g_k : g_v;
                int b_0 = r0 >> 11, s0 = r0 & 2047;
                *(uint32_t*)(P + (((size_t)(b_0 * NHEAD + h)) * S_LEN + s0) * DH + d)
                    = pack_h2(v00, v01);
                int r1 = r0 + 8;
                int b_1 = r1 >> 11, s1 = r1 & 2047;
                *(uint32_t*)(P + (((size_t)(b_1 * NHEAD + h)) * S_LEN + s1) * DH + d)
                    = pack_h2(v10, v11);
            } else {
                *(float2*)(C + (size_t)r0 * DM + col) = make_float2(v00, v01);
                *(float2*)(C + (size_t)(r0 + 8) * DM + col) = make_float2(v10, v11);
            }
        }
    }
}

// ---------------------------------------------------------------------------
// fp16 tensorized causal flash attention (unchanged from R6).
// ---------------------------------------------------------------------------
#define ASTR 72
#define QS_BYTES (128 * ASTR * 2)
#define KS_BYTES (64 * ASTR * 2)
#define ATT_SMEM (QS_BYTES + 2 * KS_BYTES)   // 36864 B

__global__ __launch_bounds__(256, 2) void attn_mma_kernel()
{
    extern __shared__ __half smh[];
    __half* Qs = smh;
    __half* Ksm = smh + 128 * ASTR;
    __half* Vsm = Ksm + 64 * ASTR;

    const int qt = (int)gridDim.x - 1 - (int)blockIdx.x;
    const int bh = blockIdx.y;
    const int tid = threadIdx.x;
    const int lane = tid & 31;
    const int w = tid >> 5;
    const int grp = lane >> 2;
    const int q = lane & 3;

    const __half* qb = g_q + (size_t)bh * S_LEN * DH + (size_t)qt * 128 * DH;
    const __half* kb = g_k + (size_t)bh * S_LEN * DH;
    const __half* vb = g_v + (size_t)bh * S_LEN * DH;

    const uint32_t qs_u = smem_u32(Qs);
    const uint32_t ks_u = smem_u32(Ksm);
    const uint32_t vs_u = smem_u32(Vsm);
    const uint32_t lm_inv = ((lane & 15) * ASTR + ((lane >> 4) << 3)) * 2;

    #pragma unroll
    for (int i = 0; i < 4; i++) {
        int c = tid + 256 * i;
        int r = c >> 3;
        int c8 = (c & 7) * 8;
        *(uint4*)(Qs + r * ASTR + c8) = *(const uint4*)(qb + r * DH + c8);
    }
    __syncthreads();

    uint32_t aq[4][4];
    #pragma unroll
    for (int ks = 0; ks < 4; ks++)
        ldsm4(aq[ks], qs_u + (w * 16 * ASTR) * 2 + ks * 32 + lm_inv);

    const int row0g = qt * 128 + w * 16 + grp;
    const int row1g = row0g + 8;
    const float scale = 0.125f;

    float m0 = -INFINITY, m1 = -INFINITY;
    float l0 = 0.0f, l1 = 0.0f;
    float ao[8][4];
    #pragma unroll
    for (int nt = 0; nt < 8; nt++)
        #pragma unroll
        for (int r = 0; r < 4; r++) ao[nt][r] = 0.0f;

    const int nkt = 2 * qt + 2;
    #pragma unroll 1
    for (int kt = 0; kt < nkt; kt++) {
        __syncthreads();
        #pragma unroll
        for (int i = 0; i < 4; i++) {
            int c = tid + 256 * i;
            int cc = c & 511;
            int r = cc >> 3;
            int c8 = (cc & 7) * 8;
            const __half* src = (c < 512) ? kb : vb;
            __half* dst = (c < 512) ? Ksm : Vsm;
            *(uint4*)(dst + r * ASTR + c8) =
                *(const uint4*)(src + (size_t)(kt * 64 + r) * DH + c8);
        }
        __syncthreads();

        float sacc[8][4];
        #pragma unroll
        for (int nt = 0; nt < 8; nt++) {
            sacc[nt][0] = 0.0f; sacc[nt][1] = 0.0f;
            sacc[nt][2] = 0.0f; sacc[nt][3] = 0.0f;
        }
        #pragma unroll
        for (int ks = 0; ks < 4; ks++) {
            #pragma unroll
            for (int p = 0; p < 4; p++) {
                uint32_t t[4];
                ldsm4(t, ks_u + (p * 16 * ASTR) * 2 + ks * 32 + lm_inv);
                uint32_t b0[2] = {t[0], t[2]};
                uint32_t b1[2] = {t[1], t[3]};
                mma_f16(sacc[2*p],     aq[ks], b0);
                mma_f16(sacc[2*p + 1], aq[ks], b1);
            }
        }
        #pragma unroll
        for (int nt = 0; nt < 8; nt++) {
            sacc[nt][0] *= scale; sacc[nt][1] *= scale;
            sacc[nt][2] *= scale; sacc[nt][3] *= scale;
        }

        if (kt >= 2 * qt) {
            #pragma unroll
            for (int nt = 0; nt < 8; nt++) {
                int c0g = kt * 64 + nt * 8 + 2 * q;
                if (c0g     > row0g) sacc[nt][0] = -INFINITY;
                if (c0g + 1 > row0g) sacc[nt][1] = -INFINITY;
                if (c0g     > row1g) sacc[nt][2] = -INFINITY;
                if (c0g + 1 > row1g) sacc[nt][3] = -INFINITY;
            }
        }

        float mt0 = -INFINITY, mt1 = -INFINITY;
        #pragma unroll
        for (int nt = 0; nt < 8; nt++) {
            mt0 = fmaxf(mt0, fmaxf(sacc[nt][0], sacc[nt][1]));
            mt1 = fmaxf(mt1, fmaxf(sacc[nt][2], sacc[nt][3]));
        }
        mt0 = fmaxf(mt0, __shfl_xor_sync(0xffffffffu, mt0, 1));
        mt0 = fmaxf(mt0, __shfl_xor_sync(0xffffffffu, mt0, 2));
        mt1 = fmaxf(mt1, __shfl_xor_sync(0xffffffffu, mt1, 1));
        mt1 = fmaxf(mt1, __shfl_xor_sync(0xffffffffu, mt1, 2));

        float mn0 = fmaxf(m0, mt0);
        float mn1 = fmaxf(m1, mt1);
        float al0 = __expf(m0 - mn0);
        float al1 = __expf(m1 - mn1);

        float rs0 = 0.0f, rs1 = 0.0f;
        #pragma unroll
        for (int nt = 0; nt < 8; nt++) {
            sacc[nt][0] = __expf(sacc[nt][0] - mn0);
            sacc[nt][1] = __expf(sacc[nt][1] - mn0);
            sacc[nt][2] = __expf(sacc[nt][2] - mn1);
            sacc[nt][3] = __expf(sacc[nt][3] - mn1);
            rs0 += sacc[nt][0] + sacc[nt][1];
            rs1 += sacc[nt][2] + sacc[nt][3];
        }
        rs0 += __shfl_xor_sync(0xffffffffu, rs0, 1);
        rs0 += __shfl_xor_sync(0xffffffffu, rs0, 2);
        rs1 += __shfl_xor_sync(0xffffffffu, rs1, 1);
        rs1 += __shfl_xor_sync(0xffffffffu, rs1, 2);

        l0 = l0 * al0 + rs0;
        l1 = l1 * al1 + rs1;
        m0 = mn0;
        m1 = mn1;

        #pragma unroll
        for (int nt = 0; nt < 8; nt++) {
            ao[nt][0] *= al0; ao[nt][1] *= al0;
            ao[nt][2] *= al1; ao[nt][3] *= al1;
        }

        uint32_t ap[4][4];
        #pragma unroll
        for (int ks = 0; ks < 4; ks++) {
            ap[ks][0] = pack_h2(sacc[2*ks][0],     sacc[2*ks][1]);
            ap[ks][1] = pack_h2(sacc[2*ks][2],     sacc[2*ks][3]);
            ap[ks][2] = pack_h2(sacc[2*ks + 1][0], sacc[2*ks + 1][1]);
            ap[ks][3] = pack_h2(sacc[2*ks + 1][2], sacc[2*ks + 1][3]);
        }

        #pragma unroll
        for (int ks = 0; ks < 4; ks++) {
            #pragma unroll
            for (int p = 0; p < 4; p++) {
                uint32_t t[4];
                ldsm4t(t, vs_u + (ks * 16 * ASTR) * 2 + p * 32 + lm_inv);
                mma_f16(ao[2*p],     ap[ks], &t[0]);
                mma_f16(ao[2*p + 1], ap[ks], &t[2]);
            }
        }
    }

    float inv0 = 1.0f / l0;
    float inv1 = 1.0f / l1;
    int b = bh >> 4;
    int h = bh & 15;
    __half* o0 = g_o + ((size_t)(b * S_LEN + row0g)) * DM + h * DH;
    __half* o1 = g_o + ((size_t)(b * S_LEN + row1g)) * DM + h * DH;
    #pragma unroll
    for (int nt = 0; nt < 8; nt++) {
        int col = nt * 8 + 2 * q;
        *(uint32_t*)(o0 + col) = pack_h2(ao[nt][0] * inv0, ao[nt][1] * inv0);
        *(uint32_t*)(o1 + col) = pack_h2(ao[nt][2] * inv1, ao[nt][3] * inv1);
    }
}

// ---------------------------------------------------------------------------
extern "C" void kernel_launch(void* const* d_in, const int* in_sizes, int n_in,
                              void* d_out, int out_size)
{
    const float* x     = (const float*)d_in[0];
    const float* W_qkv = (const float*)d_in[1];
    const float* b_qkv = (const float*)d_in[2];
    const float* W_out = (const float*)d_in[3];
    const float* b_out = (const float*)d_in[4];
    float* out = (float*)d_out;

    cudaFuncSetAttribute(attn_mma_kernel,
                         cudaFuncAttributeMaxDynamicSharedMemorySize, ATT_SMEM);
    cudaFuncSetAttribute(mma_gemm<1>,
                         cudaFuncAttributeMaxDynamicSharedMemorySize, GEMM_SMEM);
    cudaFuncSetAttribute(mma_gemm<0>,
                         cudaFuncAttributeMaxDynamicSharedMemorySize, GEMM_SMEM);

    __half* wt;  cudaGetSymbolAddress((void**)&wt, g_wt);
    __half* wo;  cudaGetSymbolAddress((void**)&wo, g_wo);
    __half* x16; cudaGetSymbolAddress((void**)&x16, g_x16);

    // 0) Weight transposes (K-major fp16) + x fp16 conversion
    {
        dim3 blk(32, 8);
        transpose_f16_kernel<<<dim3(3 * DM / 32, DM / 32), blk>>>(W_qkv, wt, DM, 3 * DM);
        transpose_f16_kernel<<<dim3(DM / 32, DM / 32), blk>>>(W_out, wo, DM, DM);
        f32_to_f16_kernel<<<(MROWS * DM) / (256 * 8), 256>>>(x, x16);
    }

    // 1) QKV projection -> fp16 scatter to g_q/g_k/g_v
    {
        dim3 grid(3 * DM / 128, MROWS / 128);   // (24, 64)
        mma_gemm<1><<<grid, 256, GEMM_SMEM>>>(b_qkv, nullptr);
    }

    // 2) fp16 tensorized causal flash attention -> g_o (fp16)
    {
        dim3 grid(S_LEN / 128, BHTOT);          // (16, 64)
        attn_mma_kernel<<<grid, 256, ATT_SMEM>>>();
    }

    // 3) Output projection -> d_out (fp32)
    {
        dim3 grid(DM / 128, MROWS / 128);       // (8, 64)
        mma_gemm<0><<<grid, 256, GEMM_SMEM>>>(b_out, out);
    }
}

// round 8
// speedup vs baseline: 7.1804x; 1.0206x over previous
#include <cuda_runtime.h>
#include <cuda_fp16.h>
#include <math.h>
#include <stdint.h>

// Problem constants
#define BATCH   4
#define S_LEN   2048
#define NHEAD   16
#define DH      64
#define DM      1024
#define BHTOT   (BATCH*NHEAD)   // 64
#define MROWS   (BATCH*S_LEN)   // 8192

// Scratch (device globals: allocation-free, graph-capturable)
__device__ __half g_q[(size_t)BHTOT * S_LEN * DH];
__device__ __half g_k[(size_t)BHTOT * S_LEN * DH];
__device__ __half g_v[(size_t)BHTOT * S_LEN * DH];
__device__ __half g_o[(size_t)MROWS * DM];
__device__ __half g_x16[(size_t)MROWS * DM];     // x converted to fp16
__device__ __half g_wt[(size_t)3 * DM * DM];     // W_qkv^T fp16 : [3072][1024]
__device__ __half g_wo[(size_t)DM * DM];         // W_out^T fp16 : [1024][1024]

// ---------------------------------------------------------------------------
__device__ __forceinline__ void mma_f16(float* c, const uint32_t* a, const uint32_t* b) {
    asm volatile(
        "mma.sync.aligned.m16n8k16.row.col.f32.f16.f16.f32 "
        "{%0,%1,%2,%3}, {%4,%5,%6,%7}, {%8,%9}, {%0,%1,%2,%3};"
        : "+f"(c[0]), "+f"(c[1]), "+f"(c[2]), "+f"(c[3])
        : "r"(a[0]), "r"(a[1]), "r"(a[2]), "r"(a[3]), "r"(b[0]), "r"(b[1]));
}
__device__ __forceinline__ void ldsm4(uint32_t* r, uint32_t addr) {
    asm volatile("ldmatrix.sync.aligned.m8n8.x4.shared.b16 {%0,%1,%2,%3}, [%4];"
                 : "=r"(r[0]), "=r"(r[1]), "=r"(r[2]), "=r"(r[3]) : "r"(addr));
}
__device__ __forceinline__ void ldsm4t(uint32_t* r, uint32_t addr) {
    asm volatile("ldmatrix.sync.aligned.m8n8.x4.trans.shared.b16 {%0,%1,%2,%3}, [%4];"
                 : "=r"(r[0]), "=r"(r[1]), "=r"(r[2]), "=r"(r[3]) : "r"(addr));
}
__device__ __forceinline__ uint32_t smem_u32(const void* p) {
    uint32_t a;
    asm("{ .reg .u64 t; cvta.to.shared.u64 t, %1; cvt.u32.u64 %0, t; }"
        : "=r"(a) : "l"(p));
    return a;
}
__device__ __forceinline__ uint32_t pack_h2(float lo, float hi) {
    __half2 h = __floats2half2_rn(lo, hi);
    return *(uint32_t*)&h;
}
__device__ __forceinline__ void cp_async16(uint32_t s, const void* g) {
    asm volatile("cp.async.cg.shared.global [%0], [%1], 16;" :: "r"(s), "l"(g));
}
__device__ __forceinline__ void cp_commit() {
    asm volatile("cp.async.commit_group;");
}
template <int N>
__device__ __forceinline__ void cp_wait() {
    asm volatile("cp.async.wait_group %0;" :: "n"(N));
}

// ---------------------------------------------------------------------------
__global__ void f32_to_f16_kernel(const float* __restrict__ in, __half* __restrict__ out)
{
    size_t i = ((size_t)blockIdx.x * blockDim.x + threadIdx.x) * 8;
    float4 a = *(const float4*)(in + i);
    float4 b = *(const float4*)(in + i + 4);
    uint4 u;
    u.x = pack_h2(a.x, a.y); u.y = pack_h2(a.z, a.w);
    u.z = pack_h2(b.x, b.y); u.w = pack_h2(b.z, b.w);
    *(uint4*)(out + i) = u;
}

__global__ void transpose_f16_kernel(const float* __restrict__ in,
                                     __half* __restrict__ out, int R, int C)
{
    __shared__ float t[32][33];
    int bx = blockIdx.x * 32, by = blockIdx.y * 32;
    int x = threadIdx.x, y0 = threadIdx.y;
    #pragma unroll
    for (int i = 0; i < 32; i += 8)
        t[y0 + i][x] = in[(size_t)(by + y0 + i) * C + bx + x];
    __syncthreads();
    #pragma unroll
    for (int i = 0; i < 32; i += 8)
        out[(size_t)(bx + y0 + i) * R + by + x] = __float2half(t[x][y0 + i]);
}

// ---------------------------------------------------------------------------
// fp16 mma.sync GEMM, 4-stage cp.async pipeline, ONE barrier per iteration.
// MODE 1: A = g_x16, B = g_wt (N=3072), scatter fp16 epilogue (Q pre-scaled)
// MODE 0: A = g_o,  B = g_wo (N=1024), C = d_out (fp32)
// ---------------------------------------------------------------------------
#define GSTR 40
#define STAGE_BYTES (128 * GSTR * 2)     // 10240
#define STAGES 4
#define GEMM_SMEM (2 * STAGES * STAGE_BYTES)   // 81920

template <int MODE>
__global__ __launch_bounds__(256, 2) void mma_gemm(
    const float* __restrict__ bias, float* __restrict__ C)
{
    extern __shared__ __half smg[];
    const uint32_t as_u = smem_u32(smg);
    const uint32_t bs_u = as_u + STAGES * STAGE_BYTES;

    const __half* Ag = (MODE == 1) ? g_x16 : g_o;
    const __half* Bg = (MODE == 1) ? g_wt : g_wo;

    const int tid = threadIdx.x;
    const int lane = tid & 31;
    const int wid = tid >> 5;
    const int wm = wid & 1;
    const int wn = wid >> 1;
    const int bm = blockIdx.y * 128;
    const int bn = blockIdx.x * 128;

    const uint32_t lm_inv = ((lane & 15) * GSTR + ((lane >> 4) << 3)) * 2;
    const int grp = lane >> 2;
    const int q = lane & 3;

    float acc[4][4][4];
    #pragma unroll
    for (int mt = 0; mt < 4; mt++)
        #pragma unroll
        for (int nt = 0; nt < 4; nt++)
            #pragma unroll
            for (int r = 0; r < 4; r++) acc[mt][nt][r] = 0.0f;

    auto issue_stage = [&](int st, int k0) {
        #pragma unroll
        for (int i = 0; i < 4; i++) {
            int c = tid + 256 * i;
            int cc = c & 511;
            int r = cc >> 2;
            int off8 = (cc & 3) * 8;
            const __half* src = ((c < 512)
                ? (Ag + (size_t)(bm + r) * 1024)
                : (Bg + (size_t)(bn + r) * 1024)) + k0 + off8;
            uint32_t dst = ((c < 512) ? as_u : bs_u)
                         + st * STAGE_BYTES + (r * GSTR + off8) * 2;
            cp_async16(dst, src);
        }
        cp_commit();
    };

    issue_stage(0, 0);
    issue_stage(1, 32);
    issue_stage(2, 64);

    #pragma unroll 1
    for (int it = 0; it < 32; it++) {
        if (it < 30) cp_wait<2>(); else cp_wait<0>();
        __syncthreads();
        // Barrier above proves all warps finished iter it-1's reads of slot
        // (it+3)&3 — safe to refill it now, overlapping with compute below.
        if (it + 3 < 32) issue_stage((it + 3) & 3, (it + 3) * 32);

        int st = it & 3;
        #pragma unroll
        for (int ks = 0; ks < 2; ks++) {
            uint32_t afr[4][4];
            #pragma unroll
            for (int mt = 0; mt < 4; mt++)
                ldsm4(afr[mt], as_u + st * STAGE_BYTES
                      + ((wm * 64 + mt * 16) * GSTR) * 2 + ks * 32 + lm_inv);
            uint32_t bfr[4][2];
            #pragma unroll
            for (int p = 0; p < 2; p++) {
                uint32_t t[4];
                ldsm4(t, bs_u + st * STAGE_BYTES
                      + ((wn * 32 + p * 16) * GSTR) * 2 + ks * 32 + lm_inv);
                bfr[2*p][0] = t[0]; bfr[2*p][1] = t[2];
                bfr[2*p+1][0] = t[1]; bfr[2*p+1][1] = t[3];
            }
            #pragma unroll
            for (int mt = 0; mt < 4; mt++)
                #pragma unroll
                for (int nt = 0; nt < 4; nt++)
                    mma_f16(acc[mt][nt], afr[mt], bfr[nt]);
        }
    }

    // Epilogue (Q scaled by 1/sqrt(Dh) at the source in MODE 1)
    #pragma unroll
    for (int mt = 0; mt < 4; mt++) {
        int r0 = bm + wm * 64 + mt * 16 + grp;
        #pragma unroll
        for (int nt = 0; nt < 4; nt++) {
            int col = bn + wn * 32 + nt * 8 + q * 2;
            float b0 = bias[col], b1 = bias[col + 1];
            float v00 = acc[mt][nt][0] + b0, v01 = acc[mt][nt][1] + b1;
            float v10 = acc[mt][nt][2] + b0, v11 = acc[mt][nt][3] + b1;
            if (MODE == 1) {
                int which = col >> 10;
                if (which == 0) {    // Q: fold in softmax scale
                    v00 *= 0.125f; v01 *= 0.125f; v10 *= 0.125f; v11 *= 0.125f;
                }
                int h = (col & 1023) >> 6;
                int d = col & 63;
                __half* P = (which == 0) ? g_q : (which == 1) ? g_k : g_v;
                int b_0 = r0 >> 11, s0 = r0 & 2047;
                *(uint32_t*)(P + (((size_t)(b_0 * NHEAD + h)) * S_LEN + s0) * DH + d)
                    = pack_h2(v00, v01);
                int r1 = r0 + 8;
                int b_1 = r1 >> 11, s1 = r1 & 2047;
                *(uint32_t*)(P + (((size_t)(b_1 * NHEAD + h)) * S_LEN + s1) * DH + d)
                    = pack_h2(v10, v11);
            } else {
                *(float2*)(C + (size_t)r0 * DM + col) = make_float2(v00, v01);
                *(float2*)(C + (size_t)(r0 + 8) * DM + col) = make_float2(v10, v11);
            }
        }
    }
}

// ---------------------------------------------------------------------------
// fp16 tensorized causal flash attention, 2-stage cp.async K/V double buffer,
// ONE barrier per key tile.  Q pre-scaled at QKV epilogue.
// ---------------------------------------------------------------------------
#define ASTR 72
#define KVB (64 * ASTR * 2)                        // 9216 B per K or V buffer
#define ATT_SMEM (128 * ASTR * 2 + 4 * KVB)        // 18432 + 36864 = 55296 B

__global__ __launch_bounds__(256, 2) void attn_mma_kernel()
{
    extern __shared__ __half smh[];
    __half* Qs = smh;                               // [128][ASTR]

    const int qt = (int)gridDim.x - 1 - (int)blockIdx.x;
    const int bh = blockIdx.y;
    const int tid = threadIdx.x;
    const int lane = tid & 31;
    const int w = tid >> 5;
    const int grp = lane >> 2;
    const int q = lane & 3;

    const __half* qb = g_q + (size_t)bh * S_LEN * DH + (size_t)qt * 128 * DH;
    const __half* kb = g_k + (size_t)bh * S_LEN * DH;
    const __half* vb = g_v + (size_t)bh * S_LEN * DH;

    const uint32_t qs_u = smem_u32(Qs);
    const uint32_t k0_u = qs_u + 128 * ASTR * 2;    // K stage 0
    const uint32_t v0_u = k0_u + 2 * KVB;           // V stage 0
    const uint32_t lm_inv = ((lane & 15) * ASTR + ((lane >> 4) << 3)) * 2;

    // Issue K/V tile kt into stage st (cp.async), 1024 16B chunks
    auto issue_kv = [&](int st, int kt) {
        #pragma unroll
        for (int i = 0; i < 4; i++) {
            int c = tid + 256 * i;
            int cc = c & 511;
            int r = cc >> 3;
            int c8 = (cc & 7) * 8;
            const __half* src = ((c < 512) ? kb : vb)
                              + (size_t)(kt * 64 + r) * DH + c8;
            uint32_t dst = ((c < 512) ? k0_u : v0_u)
                         + st * KVB + (r * ASTR + c8) * 2;
            cp_async16(dst, src);
        }
        cp_commit();
    };

    const int nkt = 2 * qt + 2;
    issue_kv(0, 0);

    // Stage Q (plain loads; overlaps with tile-0 cp.async)
    #pragma unroll
    for (int i = 0; i < 4; i++) {
        int c = tid + 256 * i;
        int r = c >> 3;
        int c8 = (c & 7) * 8;
        *(uint4*)(Qs + r * ASTR + c8) = *(const uint4*)(qb + r * DH + c8);
    }
    __syncthreads();

    uint32_t aq[4][4];
    #pragma unroll
    for (int ks = 0; ks < 4; ks++)
        ldsm4(aq[ks], qs_u + (w * 16 * ASTR) * 2 + ks * 32 + lm_inv);

    const int row0g = qt * 128 + w * 16 + grp;
    const int row1g = row0g + 8;

    float m0 = -INFINITY, m1 = -INFINITY;
    float l0 = 0.0f, l1 = 0.0f;
    float ao[8][4];
    #pragma unroll
    for (int nt = 0; nt < 8; nt++)
        #pragma unroll
        for (int r = 0; r < 4; r++) ao[nt][r] = 0.0f;

    #pragma unroll 1
    for (int kt = 0; kt < nkt; kt++) {
        cp_wait<0>();          // tile kt landed
        __syncthreads();       // all warps done with the other stage's buffers
        if (kt + 1 < nkt) issue_kv((kt + 1) & 1, kt + 1);

        const uint32_t ks_u = k0_u + (kt & 1) * KVB;
        const uint32_t vs_u = v0_u + (kt & 1) * KVB;

        // S = Q K^T (Q pre-scaled)
        float sacc[8][4];
        #pragma unroll
        for (int nt = 0; nt < 8; nt++) {
            sacc[nt][0] = 0.0f; sacc[nt][1] = 0.0f;
            sacc[nt][2] = 0.0f; sacc[nt][3] = 0.0f;
        }
        #pragma unroll
        for (int ks = 0; ks < 4; ks++) {
            #pragma unroll
            for (int p = 0; p < 4; p++) {
                uint32_t t[4];
                ldsm4(t, ks_u + (p * 16 * ASTR) * 2 + ks * 32 + lm_inv);
                uint32_t b0[2] = {t[0], t[2]};
                uint32_t b1[2] = {t[1], t[3]};
                mma_f16(sacc[2*p],     aq[ks], b0);
                mma_f16(sacc[2*p + 1], aq[ks], b1);
            }
        }

        // Causal mask (diagonal tiles only)
        if (kt >= 2 * qt) {
            #pragma unroll
            for (int nt = 0; nt < 8; nt++) {
                int c0g = kt * 64 + nt * 8 + 2 * q;
                if (c0g     > row0g) sacc[nt][0] = -INFINITY;
                if (c0g + 1 > row0g) sacc[nt][1] = -INFINITY;
                if (c0g     > row1g) sacc[nt][2] = -INFINITY;
                if (c0g + 1 > row1g) sacc[nt][3] = -INFINITY;
            }
        }

        // Online softmax
        float mt0 = -INFINITY, mt1 = -INFINITY;
        #pragma unroll
        for (int nt = 0; nt < 8; nt++) {
            mt0 = fmaxf(mt0, fmaxf(sacc[nt][0], sacc[nt][1]));
            mt1 = fmaxf(mt1, fmaxf(sacc[nt][2], sacc[nt][3]));
        }
        mt0 = fmaxf(mt0, __shfl_xor_sync(0xffffffffu, mt0, 1));
        mt0 = fmaxf(mt0, __shfl_xor_sync(0xffffffffu, mt0, 2));
        mt1 = fmaxf(mt1, __shfl_xor_sync(0xffffffffu, mt1, 1));
        mt1 = fmaxf(mt1, __shfl_xor_sync(0xffffffffu, mt1, 2));

        float mn0 = fmaxf(m0, mt0);
        float mn1 = fmaxf(m1, mt1);
        float al0 = __expf(m0 - mn0);
        float al1 = __expf(m1 - mn1);

        float rs0 = 0.0f, rs1 = 0.0f;
        #pragma unroll
        for (int nt = 0; nt < 8; nt++) {
            sacc[nt][0] = __expf(sacc[nt][0] - mn0);
            sacc[nt][1] = __expf(sacc[nt][1] - mn0);
            sacc[nt][2] = __expf(sacc[nt][2] - mn1);
            sacc[nt][3] = __expf(sacc[nt][3] - mn1);
            rs0 += sacc[nt][0] + sacc[nt][1];
            rs1 += sacc[nt][2] + sacc[nt][3];
        }
        rs0 += __shfl_xor_sync(0xffffffffu, rs0, 1);
        rs0 += __shfl_xor_sync(0xffffffffu, rs0, 2);
        rs1 += __shfl_xor_sync(0xffffffffu, rs1, 1);
        rs1 += __shfl_xor_sync(0xffffffffu, rs1, 2);

        l0 = l0 * al0 + rs0;
        l1 = l1 * al1 + rs1;
        m0 = mn0;
        m1 = mn1;

        #pragma unroll
        for (int nt = 0; nt < 8; nt++) {
            ao[nt][0] *= al0; ao[nt][1] *= al0;
            ao[nt][2] *= al1; ao[nt][3] *= al1;
        }

        // P fragments straight from S accumulators
        uint32_t ap[4][4];
        #pragma unroll
        for (int ks = 0; ks < 4; ks++) {
            ap[ks][0] = pack_h2(sacc[2*ks][0],     sacc[2*ks][1]);
            ap[ks][1] = pack_h2(sacc[2*ks][2],     sacc[2*ks][3]);
            ap[ks][2] = pack_h2(sacc[2*ks + 1][0], sacc[2*ks + 1][1]);
            ap[ks][3] = pack_h2(sacc[2*ks + 1][2], sacc[2*ks + 1][3]);
        }

        // O += P @ V (ldmatrix.trans)
        #pragma unroll
        for (int ks = 0; ks < 4; ks++) {
            #pragma unroll
            for (int p = 0; p < 4; p++) {
                uint32_t t[4];
                ldsm4t(t, vs_u + (ks * 16 * ASTR) * 2 + p * 32 + lm_inv);
                mma_f16(ao[2*p],     ap[ks], &t[0]);
                mma_f16(ao[2*p + 1], ap[ks], &t[2]);
            }
        }
    }

    float inv0 = 1.0f / l0;
    float inv1 = 1.0f / l1;
    int b = bh >> 4;
    int h = bh & 15;
    __half* o0 = g_o + ((size_t)(b * S_LEN + row0g)) * DM + h * DH;
    __half* o1 = g_o + ((size_t)(b * S_LEN + row1g)) * DM + h * DH;
    #pragma unroll
    for (int nt = 0; nt < 8; nt++) {
        int col = nt * 8 + 2 * q;
        *(uint32_t*)(o0 + col) = pack_h2(ao[nt][0] * inv0, ao[nt][1] * inv0);
        *(uint32_t*)(o1 + col) = pack_h2(ao[nt][2] * inv1, ao[nt][3] * inv1);
    }
}

// ---------------------------------------------------------------------------
extern "C" void kernel_launch(void* const* d_in, const int* in_sizes, int n_in,
                              void* d_out, int out_size)
{
    const float* x     = (const float*)d_in[0];
    const float* W_qkv = (const float*)d_in[1];
    const float* b_qkv = (const float*)d_in[2];
    const float* W_out = (const float*)d_in[3];
    const float* b_out = (const float*)d_in[4];
    float* out = (float*)d_out;

    cudaFuncSetAttribute(attn_mma_kernel,
                         cudaFuncAttributeMaxDynamicSharedMemorySize, ATT_SMEM);
    cudaFuncSetAttribute(mma_gemm<1>,
                         cudaFuncAttributeMaxDynamicSharedMemorySize, GEMM_SMEM);
    cudaFuncSetAttribute(mma_gemm<0>,
                         cudaFuncAttributeMaxDynamicSharedMemorySize, GEMM_SMEM);

    __half* wt;  cudaGetSymbolAddress((void**)&wt, g_wt);
    __half* wo;  cudaGetSymbolAddress((void**)&wo, g_wo);
    __half* x16; cudaGetSymbolAddress((void**)&x16, g_x16);

    // 0) Weight transposes (K-major fp16) + x fp16 conversion
    {
        dim3 blk(32, 8);
        transpose_f16_kernel<<<dim3(3 * DM / 32, DM / 32), blk>>>(W_qkv, wt, DM, 3 * DM);
        transpose_f16_kernel<<<dim3(DM / 32, DM / 32), blk>>>(W_out, wo, DM, DM);
        f32_to_f16_kernel<<<(MROWS * DM) / (256 * 8), 256>>>(x, x16);
    }

    // 1) QKV projection -> fp16 scatter (Q pre-scaled by 0.125)
    {
        dim3 grid(3 * DM / 128, MROWS / 128);   // (24, 64)
        mma_gemm<1><<<grid, 256, GEMM_SMEM>>>(b_qkv, nullptr);
    }

    // 2) fp16 tensorized causal flash attention -> g_o (fp16)
    {
        dim3 grid(S_LEN / 128, BHTOT);          // (16, 64)
        attn_mma_kernel<<<grid, 256, ATT_SMEM>>>();
    }

    // 3) Output projection -> d_out (fp32)
    {
        dim3 grid(DM / 128, MROWS / 128);       // (8, 64)
        mma_gemm<0><<<grid, 256, GEMM_SMEM>>>(b_out, out);
    }
}

// round 9
// speedup vs baseline: 8.1622x; 1.1367x over previous
#include <cuda_runtime.h>
#include <cuda_fp16.h>
#include <math.h>
#include <stdint.h>

// Problem constants
#define BATCH   4
#define S_LEN   2048
#define NHEAD   16
#define DH      64
#define DM      1024
#define BHTOT   (BATCH*NHEAD)   // 64
#define MROWS   (BATCH*S_LEN)   // 8192

// Scratch (device globals: allocation-free, graph-capturable)
__device__ __half g_q[(size_t)BHTOT * S_LEN * DH];
__device__ __half g_k[(size_t)BHTOT * S_LEN * DH];
__device__ __half g_v[(size_t)BHTOT * S_LEN * DH];
__device__ __half g_o[(size_t)MROWS * DM];
__device__ __half g_x16[(size_t)MROWS * DM];     // x as fp16
__device__ __half g_w16q[(size_t)DM * 3 * DM];   // W_qkv fp16, native [1024][3072]
__device__ __half g_w16o[(size_t)DM * DM];       // W_out fp16, native [1024][1024]

// ---------------------------------------------------------------------------
__device__ __forceinline__ void mma_f16(float* c, const uint32_t* a, const uint32_t* b) {
    asm volatile(
        "mma.sync.aligned.m16n8k16.row.col.f32.f16.f16.f32 "
        "{%0,%1,%2,%3}, {%4,%5,%6,%7}, {%8,%9}, {%0,%1,%2,%3};"
        : "+f"(c[0]), "+f"(c[1]), "+f"(c[2]), "+f"(c[3])
        : "r"(a[0]), "r"(a[1]), "r"(a[2]), "r"(a[3]), "r"(b[0]), "r"(b[1]));
}
__device__ __forceinline__ void ldsm4(uint32_t* r, uint32_t addr) {
    asm volatile("ldmatrix.sync.aligned.m8n8.x4.shared.b16 {%0,%1,%2,%3}, [%4];"
                 : "=r"(r[0]), "=r"(r[1]), "=r"(r[2]), "=r"(r[3]) : "r"(addr));
}
__device__ __forceinline__ void ldsm4t(uint32_t* r, uint32_t addr) {
    asm volatile("ldmatrix.sync.aligned.m8n8.x4.trans.shared.b16 {%0,%1,%2,%3}, [%4];"
                 : "=r"(r[0]), "=r"(r[1]), "=r"(r[2]), "=r"(r[3]) : "r"(addr));
}
__device__ __forceinline__ uint32_t smem_u32(const void* p) {
    uint32_t a;
    asm("{ .reg .u64 t; cvta.to.shared.u64 t, %1; cvt.u32.u64 %0, t; }"
        : "=r"(a) : "l"(p));
    return a;
}
__device__ __forceinline__ uint32_t pack_h2(float lo, float hi) {
    __half2 h = __floats2half2_rn(lo, hi);
    return *(uint32_t*)&h;
}
__device__ __forceinline__ void cp_async16(uint32_t s, const void* g) {
    asm volatile("cp.async.cg.shared.global [%0], [%1], 16;" :: "r"(s), "l"(g));
}
__device__ __forceinline__ void cp_commit() {
    asm volatile("cp.async.commit_group;");
}
template <int N>
__device__ __forceinline__ void cp_wait() {
    asm volatile("cp.async.wait_group %0;" :: "n"(N));
}

// ---------------------------------------------------------------------------
// Fused fp32 -> fp16 conversion of x, W_qkv, W_out (one launch).
// 12,582,912 elements total, 8 per thread, 6144 blocks of 256.
// ---------------------------------------------------------------------------
#define N_X   ((size_t)MROWS * DM)          // 8388608
#define N_WQ  ((size_t)DM * 3 * DM)         // 3145728
#define N_WO  ((size_t)DM * DM)             // 1048576

__global__ void preproc_f16_kernel(const float* __restrict__ x,
                                   const float* __restrict__ wq,
                                   const float* __restrict__ wo)
{
    size_t i = ((size_t)blockIdx.x * blockDim.x + threadIdx.x) * 8;
    const float* src;
    __half* dst;
    size_t off;
    if (i < N_X)            { src = x;  dst = g_x16;  off = i; }
    else if (i < N_X + N_WQ){ src = wq; dst = g_w16q; off = i - N_X; }
    else                    { src = wo; dst = g_w16o; off = i - N_X - N_WQ; }
    float4 a = *(const float4*)(src + off);
    float4 b = *(const float4*)(src + off + 4);
    uint4 u;
    u.x = pack_h2(a.x, a.y); u.y = pack_h2(a.z, a.w);
    u.z = pack_h2(b.x, b.y); u.w = pack_h2(b.z, b.w);
    *(uint4*)(dst + off) = u;
}

// ---------------------------------------------------------------------------
// fp16 mma.sync GEMM.  C[M,N] = A[M,K] @ W[K,N] + bias.  A K-major fp16,
// W native row-major fp16 (B-fragments via ldmatrix.trans).
// CTA tile 64(M)x128(N), 256 threads = 8 warps (2Mx4N), warp tile 32x32.
// BK=32, 4-stage cp.async, one barrier/iter, 3 CTAs/SM.
// MODE 1: A = g_x16, W = g_w16q (N=3072), scatter epilogue (Q pre-scaled)
// MODE 0: A = g_o,  W = g_w16o (N=1024), C = d_out (fp32)
// ---------------------------------------------------------------------------
#define GSTR 40                          // A smem stride (halves)
#define BSTR 136                         // B smem stride (halves)
#define STAGE_A (64 * GSTR * 2)          // 5120
#define STAGE_B (32 * BSTR * 2)          // 8704
#define STG_BYTES (STAGE_A + STAGE_B)    // 13824
#define STAGES 4
#define GEMM_SMEM (STAGES * STG_BYTES)   // 55296

template <int MODE>
__global__ __launch_bounds__(256, 3) void mma_gemm(
    const float* __restrict__ bias, float* __restrict__ C)
{
    extern __shared__ __half smg[];
    const uint32_t base_u = smem_u32(smg);

    const __half* Ag = (MODE == 1) ? g_x16 : g_o;
    const __half* Bg = (MODE == 1) ? g_w16q : g_w16o;
    const int NW = (MODE == 1) ? 3072 : 1024;

    const int tid = threadIdx.x;
    const int lane = tid & 31;
    const int wid = tid >> 5;
    const int wm = wid >> 2;             // 0..1 -> 32-row half
    const int wn = wid & 3;              // 0..3 -> 32-col quarter
    const int bm = blockIdx.y * 64;
    const int bn = blockIdx.x * 128;

    const uint32_t a_inv = ((lane & 15) * GSTR + ((lane >> 4) << 3)) * 2;
    const uint32_t b_inv = ((lane & 15) * BSTR + ((lane >> 4) << 3)) * 2;
    const int grp = lane >> 2;
    const int q = lane & 3;

    float acc[2][4][4];
    #pragma unroll
    for (int mt = 0; mt < 2; mt++)
        #pragma unroll
        for (int nt = 0; nt < 4; nt++)
            #pragma unroll
            for (int r = 0; r < 4; r++) acc[mt][nt][r] = 0.0f;

    // One stage: A 256 chunks (64 rows x 64B) + B 512 chunks (32 rows x 256B)
    auto issue_stage = [&](int st, int k0) {
        #pragma unroll
        for (int i = 0; i < 3; i++) {
            int c = tid + 256 * i;
            if (c < 256) {
                int r = c >> 2;
                int off8 = (c & 3) * 8;
                cp_async16(base_u + st * STG_BYTES + (r * GSTR + off8) * 2,
                           Ag + (size_t)(bm + r) * 1024 + k0 + off8);
            } else {
                int cb = c - 256;
                int r = cb >> 4;
                int off8 = (cb & 15) * 8;
                cp_async16(base_u + st * STG_BYTES + STAGE_A + (r * BSTR + off8) * 2,
                           Bg + (size_t)(k0 + r) * NW + bn + off8);
            }
        }
        cp_commit();
    };

    issue_stage(0, 0);
    issue_stage(1, 32);
    issue_stage(2, 64);

    #pragma unroll 1
    for (int it = 0; it < 32; it++) {
        if (it < 30) cp_wait<2>(); else cp_wait<0>();
        __syncthreads();
        if (it + 3 < 32) issue_stage((it + 3) & 3, (it + 3) * 32);

        const uint32_t as_u = base_u + (it & 3) * STG_BYTES;
        const uint32_t bs_u = as_u + STAGE_A;
        #pragma unroll
        for (int ks = 0; ks < 2; ks++) {
            uint32_t afr[2][4];
            #pragma unroll
            for (int mt = 0; mt < 2; mt++)
                ldsm4(afr[mt], as_u + ((wm * 32 + mt * 16) * GSTR) * 2
                      + ks * 32 + a_inv);
            #pragma unroll
            for (int p = 0; p < 2; p++) {
                uint32_t t[4];
                ldsm4t(t, bs_u + (ks * 16 * BSTR) * 2
                       + wn * 64 + p * 32 + b_inv);
                #pragma unroll
                for (int mt = 0; mt < 2; mt++) {
                    mma_f16(acc[mt][2*p],     afr[mt], &t[0]);
                    mma_f16(acc[mt][2*p + 1], afr[mt], &t[2]);
                }
            }
        }
    }

    // Epilogue
    #pragma unroll
    for (int mt = 0; mt < 2; mt++) {
        int r0 = bm + wm * 32 + mt * 16 + grp;
        #pragma unroll
        for (int nt = 0; nt < 4; nt++) {
            int col = bn + wn * 32 + nt * 8 + q * 2;
            float b0 = bias[col], b1 = bias[col + 1];
            float v00 = acc[mt][nt][0] + b0, v01 = acc[mt][nt][1] + b1;
            float v10 = acc[mt][nt][2] + b0, v11 = acc[mt][nt][3] + b1;
            if (MODE == 1) {
                int which = col >> 10;
                if (which == 0) {    // Q: fold in softmax scale
                    v00 *= 0.125f; v01 *= 0.125f; v10 *= 0.125f; v11 *= 0.125f;
                }
                int h = (col & 1023) >> 6;
                int d = col & 63;
                __half* P = (which == 0) ? g_q : (which == 1) ? g_k : g_v;
                int b_0 = r0 >> 11, s0 = r0 & 2047;
                *(uint32_t*)(P + (((size_t)(b_0 * NHEAD + h)) * S_LEN + s0) * DH + d)
                    = pack_h2(v00, v01);
                int r1 = r0 + 8;
                int b_1 = r1 >> 11, s1 = r1 & 2047;
                *(uint32_t*)(P + (((size_t)(b_1 * NHEAD + h)) * S_LEN + s1) * DH + d)
                    = pack_h2(v10, v11);
            } else {
                *(float2*)(C + (size_t)r0 * DM + col) = make_float2(v00, v01);
                *(float2*)(C + (size_t)(r0 + 8) * DM + col) = make_float2(v10, v11);
            }
        }
    }
}

// ---------------------------------------------------------------------------
// fp16 tensorized causal flash attention (unchanged from R8).
// ---------------------------------------------------------------------------
#define ASTR 72
#define KVB (64 * ASTR * 2)                        // 9216 B per K or V buffer
#define ATT_SMEM (128 * ASTR * 2 + 4 * KVB)        // 55296 B

__global__ __launch_bounds__(256, 2) void attn_mma_kernel()
{
    extern __shared__ __half smh[];
    __half* Qs = smh;

    const int qt = (int)gridDim.x - 1 - (int)blockIdx.x;
    const int bh = blockIdx.y;
    const int tid = threadIdx.x;
    const int lane = tid & 31;
    const int w = tid >> 5;
    const int grp = lane >> 2;
    const int q = lane & 3;

    const __half* qb = g_q + (size_t)bh * S_LEN * DH + (size_t)qt * 128 * DH;
    const __half* kb = g_k + (size_t)bh * S_LEN * DH;
    const __half* vb = g_v + (size_t)bh * S_LEN * DH;

    const uint32_t qs_u = smem_u32(Qs);
    const uint32_t k0_u = qs_u + 128 * ASTR * 2;
    const uint32_t v0_u = k0_u + 2 * KVB;
    const uint32_t lm_inv = ((lane & 15) * ASTR + ((lane >> 4) << 3)) * 2;

    auto issue_kv = [&](int st, int kt) {
        #pragma unroll
        for (int i = 0; i < 4; i++) {
            int c = tid + 256 * i;
            int cc = c & 511;
            int r = cc >> 3;
            int c8 = (cc & 7) * 8;
            const __half* src = ((c < 512) ? kb : vb)
                              + (size_t)(kt * 64 + r) * DH + c8;
            uint32_t dst = ((c < 512) ? k0_u : v0_u)
                         + st * KVB + (r * ASTR + c8) * 2;
            cp_async16(dst, src);
        }
        cp_commit();
    };

    const int nkt = 2 * qt + 2;
    issue_kv(0, 0);

    #pragma unroll
    for (int i = 0; i < 4; i++) {
        int c = tid + 256 * i;
        int r = c >> 3;
        int c8 = (c & 7) * 8;
        *(uint4*)(Qs + r * ASTR + c8) = *(const uint4*)(qb + r * DH + c8);
    }
    __syncthreads();

    uint32_t aq[4][4];
    #pragma unroll
    for (int ks = 0; ks < 4; ks++)
        ldsm4(aq[ks], qs_u + (w * 16 * ASTR) * 2 + ks * 32 + lm_inv);

    const int row0g = qt * 128 + w * 16 + grp;
    const int row1g = row0g + 8;

    float m0 = -INFINITY, m1 = -INFINITY;
    float l0 = 0.0f, l1 = 0.0f;
    float ao[8][4];
    #pragma unroll
    for (int nt = 0; nt < 8; nt++)
        #pragma unroll
        for (int r = 0; r < 4; r++) ao[nt][r] = 0.0f;

    #pragma unroll 1
    for (int kt = 0; kt < nkt; kt++) {
        cp_wait<0>();
        __syncthreads();
        if (kt + 1 < nkt) issue_kv((kt + 1) & 1, kt + 1);

        const uint32_t ks_u = k0_u + (kt & 1) * KVB;
        const uint32_t vs_u = v0_u + (kt & 1) * KVB;

        float sacc[8][4];
        #pragma unroll
        for (int nt = 0; nt < 8; nt++) {
            sacc[nt][0] = 0.0f; sacc[nt][1] = 0.0f;
            sacc[nt][2] = 0.0f; sacc[nt][3] = 0.0f;
        }
        #pragma unroll
        for (int ks = 0; ks < 4; ks++) {
            #pragma unroll
            for (int p = 0; p < 4; p++) {
                uint32_t t[4];
                ldsm4(t, ks_u + (p * 16 * ASTR) * 2 + ks * 32 + lm_inv);
                uint32_t b0[2] = {t[0], t[2]};
                uint32_t b1[2] = {t[1], t[3]};
                mma_f16(sacc[2*p],     aq[ks], b0);
                mma_f16(sacc[2*p + 1], aq[ks], b1);
            }
        }

        if (kt >= 2 * qt) {
            #pragma unroll
            for (int nt = 0; nt < 8; nt++) {
                int c0g = kt * 64 + nt * 8 + 2 * q;
                if (c0g     > row0g) sacc[nt][0] = -INFINITY;
                if (c0g + 1 > row0g) sacc[nt][1] = -INFINITY;
                if (c0g     > row1g) sacc[nt][2] = -INFINITY;
                if (c0g + 1 > row1g) sacc[nt][3] = -INFINITY;
            }
        }

        float mt0 = -INFINITY, mt1 = -INFINITY;
        #pragma unroll
        for (int nt = 0; nt < 8; nt++) {
            mt0 = fmaxf(mt0, fmaxf(sacc[nt][0], sacc[nt][1]));
            mt1 = fmaxf(mt1, fmaxf(sacc[nt][2], sacc[nt][3]));
        }
        mt0 = fmaxf(mt0, __shfl_xor_sync(0xffffffffu, mt0, 1));
        mt0 = fmaxf(mt0, __shfl_xor_sync(0xffffffffu, mt0, 2));
        mt1 = fmaxf(mt1, __shfl_xor_sync(0xffffffffu, mt1, 1));
        mt1 = fmaxf(mt1, __shfl_xor_sync(0xffffffffu, mt1, 2));

        float mn0 = fmaxf(m0, mt0);
        float mn1 = fmaxf(m1, mt1);
        float al0 = __expf(m0 - mn0);
        float al1 = __expf(m1 - mn1);

        float rs0 = 0.0f, rs1 = 0.0f;
        #pragma unroll
        for (int nt = 0; nt < 8; nt++) {
            sacc[nt][0] = __expf(sacc[nt][0] - mn0);
            sacc[nt][1] = __expf(sacc[nt][1] - mn0);
            sacc[nt][2] = __expf(sacc[nt][2] - mn1);
            sacc[nt][3] = __expf(sacc[nt][3] - mn1);
            rs0 += sacc[nt][0] + sacc[nt][1];
            rs1 += sacc[nt][2] + sacc[nt][3];
        }
        rs0 += __shfl_xor_sync(0xffffffffu, rs0, 1);
        rs0 += __shfl_xor_sync(0xffffffffu, rs0, 2);
        rs1 += __shfl_xor_sync(0xffffffffu, rs1, 1);
        rs1 += __shfl_xor_sync(0xffffffffu, rs1, 2);

        l0 = l0 * al0 + rs0;
        l1 = l1 * al1 + rs1;
        m0 = mn0;
        m1 = mn1;

        #pragma unroll
        for (int nt = 0; nt < 8; nt++) {
            ao[nt][0] *= al0; ao[nt][1] *= al0;
            ao[nt][2] *= al1; ao[nt][3] *= al1;
        }

        uint32_t ap[4][4];
        #pragma unroll
        for (int ks = 0; ks < 4; ks++) {
            ap[ks][0] = pack_h2(sacc[2*ks][0],     sacc[2*ks][1]);
            ap[ks][1] = pack_h2(sacc[2*ks][2],     sacc[2*ks][3]);
            ap[ks][2] = pack_h2(sacc[2*ks + 1][0], sacc[2*ks + 1][1]);
            ap[ks][3] = pack_h2(sacc[2*ks + 1][2], sacc[2*ks + 1][3]);
        }

        #pragma unroll
        for (int ks = 0; ks < 4; ks++) {
            #pragma unroll
            for (int p = 0; p < 4; p++) {
                uint32_t t[4];
                ldsm4t(t, vs_u + (ks * 16 * ASTR) * 2 + p * 32 + lm_inv);
                mma_f16(ao[2*p],     ap[ks], &t[0]);
                mma_f16(ao[2*p + 1], ap[ks], &t[2]);
            }
        }
    }

    float inv0 = 1.0f / l0;
    float inv1 = 1.0f / l1;
    int b = bh >> 4;
    int h = bh & 15;
    __half* o0 = g_o + ((size_t)(b * S_LEN + row0g)) * DM + h * DH;
    __half* o1 = g_o + ((size_t)(b * S_LEN + row1g)) * DM + h * DH;
    #pragma unroll
    for (int nt = 0; nt < 8; nt++) {
        int col = nt * 8 + 2 * q;
        *(uint32_t*)(o0 + col) = pack_h2(ao[nt][0] * inv0, ao[nt][1] * inv0);
        *(uint32_t*)(o1 + col) = pack_h2(ao[nt][2] * inv1, ao[nt][3] * inv1);
    }
}

// ---------------------------------------------------------------------------
extern "C" void kernel_launch(void* const* d_in, const int* in_sizes, int n_in,
                              void* d_out, int out_size)
{
    const float* x     = (const float*)d_in[0];
    const float* W_qkv = (const float*)d_in[1];
    const float* b_qkv = (const float*)d_in[2];
    const float* W_out = (const float*)d_in[3];
    const float* b_out = (const float*)d_in[4];
    float* out = (float*)d_out;

    cudaFuncSetAttribute(attn_mma_kernel,
                         cudaFuncAttributeMaxDynamicSharedMemorySize, ATT_SMEM);
    cudaFuncSetAttribute(mma_gemm<1>,
                         cudaFuncAttributeMaxDynamicSharedMemorySize, GEMM_SMEM);
    cudaFuncSetAttribute(mma_gemm<0>,
                         cudaFuncAttributeMaxDynamicSharedMemorySize, GEMM_SMEM);

    // 0) Fused fp16 conversion: x, W_qkv (native layout), W_out (native layout)
    {
        int total = (int)((N_X + N_WQ + N_WO) / 8 / 256);   // 6144 blocks
        preproc_f16_kernel<<<total, 256>>>(x, W_qkv, W_out);
    }

    // 1) QKV projection -> fp16 scatter (Q pre-scaled by 0.125)
    {
        dim3 grid(3 * DM / 128, MROWS / 64);    // (24, 128)
        mma_gemm<1><<<grid, 256, GEMM_SMEM>>>(b_qkv, nullptr);
    }

    // 2) fp16 tensorized causal flash attention -> g_o (fp16)
    {
        dim3 grid(S_LEN / 128, BHTOT);          // (16, 64)
        attn_mma_kernel<<<grid, 256, ATT_SMEM>>>();
    }

    // 3) Output projection -> d_out (fp32)
    {
        dim3 grid(DM / 128, MROWS / 64);        // (8, 128)
        mma_gemm<0><<<grid, 256, GEMM_SMEM>>>(b_out, out);
    }
}